// round 15
// baseline (speedup 1.0000x reference)
#include <cuda_runtime.h>
#include <cuda_fp16.h>
#include <math.h>
#include <stdint.h>

#define S_LEN 2048
#define D_DIM 1024
#define B_SZ  2
#define NH    16
#define DHE   64
#define WIN   128
#define NTOK  (B_SZ * S_LEN)   // 4096
#define D3    (3 * D_DIM)      // 3072

#define SMAP(i) ((i) + ((i) >> 4))

// ---------------- scratch ----------------
__device__ float  g_qkv[(size_t)NTOK * D3];
__device__ __half g_attn_h[(size_t)NTOK * D_DIM];
__device__ float  g_attnout[(size_t)NTOK * D_DIM];
__device__ float  g_xwave[(size_t)NTOK * D_DIM];
__device__ __half g_xh[(size_t)NTOK * D_DIM];
__device__ __half g_wh_in[(size_t)D3 * D_DIM];
__device__ __half g_wh_out[(size_t)D_DIM * D_DIM];

// ---------------- helpers ----------------
__device__ __forceinline__ uint32_t smem_u32(const void* p) {
    uint32_t a;
    asm("{ .reg .u64 t; cvta.to.shared.u64 t, %1; cvt.u32.u64 %0, t; }" : "=r"(a) : "l"(p));
    return a;
}
__device__ __forceinline__ void cpasync16(uint32_t dst, const void* src) {
    asm volatile("cp.async.ca.shared.global [%0], [%1], 16;" :: "r"(dst), "l"(src));
}
#define CP_COMMIT() asm volatile("cp.async.commit_group;" ::: "memory")
#define CP_WAIT1()  asm volatile("cp.async.wait_group 1;" ::: "memory")

__device__ __forceinline__ uint32_t f22h2(float a, float b) {
    __half2 h = __floats2half2_rn(a, b);
    return *(uint32_t*)&h;
}
__device__ __forceinline__ uint32_t f2tf(float f) {
    uint32_t u;
    asm("cvt.rna.tf32.f32 %0, %1;" : "=r"(u) : "f"(f));
    return u;
}
__device__ __forceinline__ void mma_fp16(
    float& c0, float& c1, float& c2, float& c3,
    uint32_t a0, uint32_t a1, uint32_t a2, uint32_t a3,
    uint32_t b0, uint32_t b1)
{
    asm volatile(
        "mma.sync.aligned.m16n8k16.row.col.f32.f16.f16.f32 "
        "{%0,%1,%2,%3}, {%4,%5,%6,%7}, {%8,%9}, {%0,%1,%2,%3};\n"
        : "+f"(c0), "+f"(c1), "+f"(c2), "+f"(c3)
        : "r"(a0), "r"(a1), "r"(a2), "r"(a3), "r"(b0), "r"(b1));
}
__device__ __forceinline__ void mma_tf32(
    float& c0, float& c1, float& c2, float& c3,
    uint32_t a0, uint32_t a1, uint32_t a2, uint32_t a3,
    uint32_t b0, uint32_t b1)
{
    asm volatile(
        "mma.sync.aligned.m16n8k8.row.col.f32.tf32.tf32.f32 "
        "{%0,%1,%2,%3}, {%4,%5,%6,%7}, {%8,%9}, {%0,%1,%2,%3};\n"
        : "+f"(c0), "+f"(c1), "+f"(c2), "+f"(c3)
        : "r"(a0), "r"(a1), "r"(a2), "r"(a3), "r"(b0), "r"(b1));
}

// ---------------- f32 -> f16 convert ----------------
__global__ void __launch_bounds__(256) conv_f2h(const float* __restrict__ src,
                                               __half* __restrict__ dst, int n)
{
    int i = (blockIdx.x * 256 + threadIdx.x) * 4;
    if (i < n) {
        float4 v = *(const float4*)(src + i);
        *(uint2*)(dst + i) = make_uint2(f22h2(v.x, v.y), f22h2(v.z, v.w));
    }
}

// ---------------- complex helpers ----------------
__device__ __forceinline__ float2 cmul(float2 a, float2 b) {
    return make_float2(a.x * b.x - a.y * b.y, a.x * b.y + a.y * b.x);
}
__device__ __forceinline__ float2 cadd(float2 a, float2 b) {
    return make_float2(a.x + b.x, a.y + b.y);
}
__device__ __forceinline__ float2 csub(float2 a, float2 b) {
    return make_float2(a.x - b.x, a.y - b.y);
}

// fused radix-8 Stockham (validated round 13)
template<int SIGN>
__device__ __forceinline__ void fft2048_r8(float2*& cur, float2*& oth)
{
    const float C8 = 0.70710678118654752f;
    const float SG = (float)SIGN;
#pragma unroll
    for (int st = 0; st < 3; st++) {
        const int ls = st * 3;
        const int ss = 1 << ls;
        const int n  = 2048 >> ls;
        const float fn = (2.0f * 3.14159265358979f * SG) / (float)n;
        const int idx = threadIdx.x;
        const int p = idx >> ls;
        const int q = idx & (ss - 1);

        float2 x0 = cur[SMAP(idx)];
        float2 x1 = cur[SMAP(idx + 256)];
        float2 x2 = cur[SMAP(idx + 512)];
        float2 x3 = cur[SMAP(idx + 768)];
        float2 x4 = cur[SMAP(idx + 1024)];
        float2 x5 = cur[SMAP(idx + 1280)];
        float2 x6 = cur[SMAP(idx + 1536)];
        float2 x7 = cur[SMAP(idx + 1792)];

        float2 es = cadd(x0, x4), ed = csub(x0, x4);
        float2 fs = cadd(x2, x6), fd = csub(x2, x6);
        float2 E0 = cadd(es, fs);
        float2 E2 = csub(es, fs);
        float2 E1 = make_float2(ed.x - SG * fd.y, ed.y + SG * fd.x);
        float2 E3 = make_float2(ed.x + SG * fd.y, ed.y - SG * fd.x);
        float2 os = cadd(x1, x5), od = csub(x1, x5);
        float2 gs = cadd(x3, x7), gd = csub(x3, x7);
        float2 O0 = cadd(os, gs);
        float2 O2 = csub(os, gs);
        float2 O1 = make_float2(od.x - SG * gd.y, od.y + SG * gd.x);
        float2 O3 = make_float2(od.x + SG * gd.y, od.y - SG * gd.x);
        float2 t0 = O0;
        float2 t1 = make_float2(C8 * (O1.x - SG * O1.y), C8 * (SG * O1.x + O1.y));
        float2 t2 = make_float2(-SG * O2.y, SG * O2.x);
        float2 t3 = make_float2(C8 * (-O3.x - SG * O3.y), C8 * (SG * O3.x - O3.y));

        float2 X0 = cadd(E0, t0), X4 = csub(E0, t0);
        float2 X1 = cadd(E1, t1), X5 = csub(E1, t1);
        float2 X2 = cadd(E2, t2), X6 = csub(E2, t2);
        float2 X3 = cadd(E3, t3), X7 = csub(E3, t3);

        float sn, cs;
        __sincosf(fn * (float)p, &sn, &cs);
        const float2 w1 = make_float2(cs, sn);
        const float2 w2 = cmul(w1, w1);
        const float2 w3 = cmul(w1, w2);
        const float2 w4 = cmul(w2, w2);
        const float2 w5 = cmul(w2, w3);
        const float2 w6 = cmul(w3, w3);
        const float2 w7 = cmul(w3, w4);

        const int ob = q + 8 * ss * p;
        oth[SMAP(ob)]          = X0;
        oth[SMAP(ob + ss)]     = cmul(X1, w1);
        oth[SMAP(ob + 2 * ss)] = cmul(X2, w2);
        oth[SMAP(ob + 3 * ss)] = cmul(X3, w3);
        oth[SMAP(ob + 4 * ss)] = cmul(X4, w4);
        oth[SMAP(ob + 5 * ss)] = cmul(X5, w5);
        oth[SMAP(ob + 6 * ss)] = cmul(X6, w6);
        oth[SMAP(ob + 7 * ss)] = cmul(X7, w7);

        __syncthreads();
        float2* tmp = cur; cur = oth; oth = tmp;
    }
#pragma unroll
    for (int ii = 0; ii < 2; ii++) {
        const int qq = threadIdx.x + 256 * ii;
        float2 x0 = cur[SMAP(qq)];
        float2 x1 = cur[SMAP(qq + 512)];
        float2 x2 = cur[SMAP(qq + 1024)];
        float2 x3 = cur[SMAP(qq + 1536)];
        float2 a0 = cadd(x0, x2), a1 = csub(x0, x2);
        float2 b0 = cadd(x1, x3), u = csub(x1, x3);
        float2 b1 = make_float2(-SG * u.y, SG * u.x);
        oth[SMAP(qq)]        = cadd(a0, b0);
        oth[SMAP(qq + 512)]  = cadd(a1, b1);
        oth[SMAP(qq + 1024)] = csub(a0, b0);
        oth[SMAP(qq + 1536)] = csub(a1, b1);
    }
    __syncthreads();
    { float2* tmp = cur; cur = oth; oth = tmp; }
}

// ---------------- fused QKV GEMM + spectral, INTERLEAVED blocks ----------------
// 1792 blocks = 256 groups of 7: 3 GEMM + 4 spectral per group, so every
// resident wave mixes tensor-bound GEMM CTAs with latency-bound FFT CTAs.
#define LDP 20
#define STG 3
#define GEMM_BX (D3 / 128)                     // 24
#define GEMM_BLOCKS (GEMM_BX * (NTOK / 128))   // 768
#define TOTAL_BLOCKS (GEMM_BLOCKS + 1024)      // 1792 = 256 * 7

union SmemU {
    struct { uint32_t As2[STG][128][LDP]; uint32_t Ws2[STG][128][LDP]; } g;  // 61440 B
    struct { float2 bufA[2176]; float2 bufB[2176]; } s;                      // 34816 B
};

__global__ void __launch_bounds__(256, 2) fused_qkv_spec(
    const __half* __restrict__ A, const __half* __restrict__ W,
    const float* __restrict__ bias, float* __restrict__ C,
    const float* __restrict__ x, const float* __restrict__ wr,
    const float* __restrict__ wi, float* __restrict__ xwave)
{
    __shared__ SmemU u;
    const int t   = threadIdx.x;
    const int grp = blockIdx.x / 7;
    const int rem = blockIdx.x % 7;

    if (rem < 3) {
        // ================= QKV GEMM path (M=NTOK, N=D3, K=D_DIM) =================
        const int gid  = grp * 3 + rem;          // 0..767
        const int  N = D3, K = D_DIM;
        const int row0 = (gid / GEMM_BX) * 128;
        const int col0 = (gid % GEMM_BX) * 128;
        const int warp = t >> 5;
        const int lane = t & 31;
        const int gr   = lane >> 2;
        const int tc   = lane & 3;
        const int m0w  = (warp >> 2) * 64;
        const int n0w  = (warp & 3) * 32;

        const int r0c = t >> 2;          const int c0c = t & 3;
        const int r1c = (t + 256) >> 2;  const int c1c = (t + 256) & 3;

        const __half* Ar0 = A + (size_t)(row0 + r0c) * K + c0c * 8;
        const __half* Ar1 = A + (size_t)(row0 + r1c) * K + c1c * 8;
        const __half* Wr0 = W + (size_t)(col0 + r0c) * K + c0c * 8;
        const __half* Wr1 = W + (size_t)(col0 + r1c) * K + c1c * 8;

        float acc[4][4][4];
#pragma unroll
        for (int mi = 0; mi < 4; mi++)
#pragma unroll
            for (int ni = 0; ni < 4; ni++)
#pragma unroll
                for (int r = 0; r < 4; r++) acc[mi][ni][r] = 0.f;

        const int ntiles = K >> 5;

#pragma unroll
        for (int s = 0; s < 2; s++) {
            const int k0 = s << 5;
            cpasync16(smem_u32(&u.g.As2[s][r0c][c0c * 4]), Ar0 + k0);
            cpasync16(smem_u32(&u.g.As2[s][r1c][c1c * 4]), Ar1 + k0);
            cpasync16(smem_u32(&u.g.Ws2[s][r0c][c0c * 4]), Wr0 + k0);
            cpasync16(smem_u32(&u.g.Ws2[s][r1c][c1c * 4]), Wr1 + k0);
            CP_COMMIT();
        }

        int cb = 0, nst = 2;
        for (int kt = 0; kt < ntiles; kt++) {
            CP_WAIT1();
            __syncthreads();

            if (kt + 2 < ntiles) {
                const int k0 = (kt + 2) << 5;
                cpasync16(smem_u32(&u.g.As2[nst][r0c][c0c * 4]), Ar0 + k0);
                cpasync16(smem_u32(&u.g.As2[nst][r1c][c1c * 4]), Ar1 + k0);
                cpasync16(smem_u32(&u.g.Ws2[nst][r0c][c0c * 4]), Wr0 + k0);
                cpasync16(smem_u32(&u.g.Ws2[nst][r1c][c1c * 4]), Wr1 + k0);
            }
            CP_COMMIT();

#pragma unroll
            for (int kk = 0; kk < 2; kk++) {
                uint32_t af[4][4];
#pragma unroll
                for (int mi = 0; mi < 4; mi++) {
                    const int br = m0w + mi * 16;
                    af[mi][0] = u.g.As2[cb][br + gr][kk * 8 + tc];
                    af[mi][1] = u.g.As2[cb][br + gr + 8][kk * 8 + tc];
                    af[mi][2] = u.g.As2[cb][br + gr][kk * 8 + tc + 4];
                    af[mi][3] = u.g.As2[cb][br + gr + 8][kk * 8 + tc + 4];
                }
                uint32_t bf[4][2];
#pragma unroll
                for (int ni = 0; ni < 4; ni++) {
                    const int bn = n0w + ni * 8 + gr;
                    bf[ni][0] = u.g.Ws2[cb][bn][kk * 8 + tc];
                    bf[ni][1] = u.g.Ws2[cb][bn][kk * 8 + tc + 4];
                }
#pragma unroll
                for (int mi = 0; mi < 4; mi++)
#pragma unroll
                    for (int ni = 0; ni < 4; ni++)
                        mma_fp16(acc[mi][ni][0], acc[mi][ni][1], acc[mi][ni][2], acc[mi][ni][3],
                                 af[mi][0], af[mi][1], af[mi][2], af[mi][3],
                                 bf[ni][0], bf[ni][1]);
            }

            cb  = (cb  + 1) % STG;
            nst = (nst + 1) % STG;
        }

#pragma unroll
        for (int mi = 0; mi < 4; mi++) {
#pragma unroll
            for (int ni = 0; ni < 4; ni++) {
                const int r = row0 + m0w + mi * 16 + gr;
                const int c = col0 + n0w + ni * 8 + tc * 2;
                float2 bs = *(const float2*)(bias + c);
                float2 v0 = make_float2(acc[mi][ni][0] + bs.x, acc[mi][ni][1] + bs.y);
                float2 v1 = make_float2(acc[mi][ni][2] + bs.x, acc[mi][ni][3] + bs.y);
                *(float2*)(C + (size_t)r * N + c)       = v0;
                *(float2*)(C + (size_t)(r + 8) * N + c) = v1;
            }
        }
    } else {
        // ================= spectral path =================
        const int sid = grp * 4 + (rem - 3);     // 0..1023
        const int d0 = (sid & 511) * 2;
        const int b  = sid >> 9;

        float2* bufA = u.s.bufA;
        float2* bufB = u.s.bufB;

        const float* xp = x + (size_t)b * S_LEN * D_DIM + d0;
        for (int s = t; s < 2048; s += 256)
            bufA[SMAP(s)] = *(const float2*)(xp + (size_t)s * D_DIM);
        __syncthreads();

        float2* cur = bufA;
        float2* oth = bufB;
        fft2048_r8<-1>(cur, oth);

        for (int k = t; k < 2048; k += 256) {
            const int km = (2048 - k) & 2047;
            float2 Zk = cur[SMAP(k)];
            float2 Zm = cur[SMAP(km)];
            float2 Av = make_float2(0.5f * (Zk.x + Zm.x), 0.5f * (Zk.y - Zm.y));
            float2 Bc = make_float2(0.5f * (Zk.y + Zm.y), -0.5f * (Zk.x - Zm.x));
            const int   kf  = (k <= 1024) ? k : 2048 - k;
            const float sgn = (k <= 1024) ? 1.f : -1.f;
            float2 wrp = *(const float2*)(wr + (size_t)kf * D_DIM + d0);
            float2 wip = *(const float2*)(wi + (size_t)kf * D_DIM + d0);
            float2 c1 = make_float2(wrp.x, sgn * wip.x);
            float2 c2 = make_float2(wrp.y, sgn * wip.y);
            if (k == 0 || k == 1024) { c1.y = 0.f; c2.y = 0.f; }
            float2 Y1 = cmul(Av, c1);
            float2 Y2 = cmul(Bc, c2);
            oth[SMAP(k)] = make_float2(Y1.x - Y2.y, Y1.y + Y2.x);
        }
        __syncthreads();
        { float2* tmp = cur; cur = oth; oth = tmp; }

        fft2048_r8<1>(cur, oth);

        float* dst = xwave + (size_t)b * S_LEN * D_DIM + d0;
        const float invn = 1.0f / 2048.0f;
        for (int s = t; s < 2048; s += 256) {
            float2 r = cur[SMAP(s)];
            *(float2*)(dst + (size_t)s * D_DIM) = make_float2(r.x * invn, r.y * invn);
        }
    }
}

// ---------------- fp16 GEMM, 3-stage cp.async pipeline (out-proj) ----------------
__global__ void __launch_bounds__(256, 2) gemm_fp16_pipe(
    const __half* __restrict__ A, const __half* __restrict__ W,
    const float* __restrict__ bias, float* __restrict__ C,
    int M, int N, int K)
{
    __shared__ uint32_t As2[STG][128][LDP];
    __shared__ uint32_t Ws2[STG][128][LDP];

    const int row0 = blockIdx.y * 128;
    const int col0 = blockIdx.x * 128;
    const int t    = threadIdx.x;
    const int warp = t >> 5;
    const int lane = t & 31;
    const int gr   = lane >> 2;
    const int tc   = lane & 3;
    const int m0w  = (warp >> 2) * 64;
    const int n0w  = (warp & 3) * 32;

    const int r0c = t >> 2;          const int c0c = t & 3;
    const int r1c = (t + 256) >> 2;  const int c1c = (t + 256) & 3;

    const __half* Ar0 = A + (size_t)(row0 + r0c) * K + c0c * 8;
    const __half* Ar1 = A + (size_t)(row0 + r1c) * K + c1c * 8;
    const __half* Wr0 = W + (size_t)(col0 + r0c) * K + c0c * 8;
    const __half* Wr1 = W + (size_t)(col0 + r1c) * K + c1c * 8;

    float acc[4][4][4];
#pragma unroll
    for (int mi = 0; mi < 4; mi++)
#pragma unroll
        for (int ni = 0; ni < 4; ni++)
#pragma unroll
            for (int r = 0; r < 4; r++) acc[mi][ni][r] = 0.f;

    const int ntiles = K >> 5;

#pragma unroll
    for (int s = 0; s < 2; s++) {
        const int k0 = s << 5;
        cpasync16(smem_u32(&As2[s][r0c][c0c * 4]), Ar0 + k0);
        cpasync16(smem_u32(&As2[s][r1c][c1c * 4]), Ar1 + k0);
        cpasync16(smem_u32(&Ws2[s][r0c][c0c * 4]), Wr0 + k0);
        cpasync16(smem_u32(&Ws2[s][r1c][c1c * 4]), Wr1 + k0);
        CP_COMMIT();
    }

    int cb = 0, nst = 2;
    for (int kt = 0; kt < ntiles; kt++) {
        CP_WAIT1();
        __syncthreads();

        if (kt + 2 < ntiles) {
            const int k0 = (kt + 2) << 5;
            cpasync16(smem_u32(&As2[nst][r0c][c0c * 4]), Ar0 + k0);
            cpasync16(smem_u32(&As2[nst][r1c][c1c * 4]), Ar1 + k0);
            cpasync16(smem_u32(&Ws2[nst][r0c][c0c * 4]), Wr0 + k0);
            cpasync16(smem_u32(&Ws2[nst][r1c][c1c * 4]), Wr1 + k0);
        }
        CP_COMMIT();

#pragma unroll
        for (int kk = 0; kk < 2; kk++) {
            uint32_t af[4][4];
#pragma unroll
            for (int mi = 0; mi < 4; mi++) {
                const int br = m0w + mi * 16;
                af[mi][0] = As2[cb][br + gr][kk * 8 + tc];
                af[mi][1] = As2[cb][br + gr + 8][kk * 8 + tc];
                af[mi][2] = As2[cb][br + gr][kk * 8 + tc + 4];
                af[mi][3] = As2[cb][br + gr + 8][kk * 8 + tc + 4];
            }
            uint32_t bf[4][2];
#pragma unroll
            for (int ni = 0; ni < 4; ni++) {
                const int bn = n0w + ni * 8 + gr;
                bf[ni][0] = Ws2[cb][bn][kk * 8 + tc];
                bf[ni][1] = Ws2[cb][bn][kk * 8 + tc + 4];
            }
#pragma unroll
            for (int mi = 0; mi < 4; mi++)
#pragma unroll
                for (int ni = 0; ni < 4; ni++)
                    mma_fp16(acc[mi][ni][0], acc[mi][ni][1], acc[mi][ni][2], acc[mi][ni][3],
                             af[mi][0], af[mi][1], af[mi][2], af[mi][3],
                             bf[ni][0], bf[ni][1]);
        }

        cb  = (cb  + 1) % STG;
        nst = (nst + 1) % STG;
    }

#pragma unroll
    for (int mi = 0; mi < 4; mi++) {
#pragma unroll
        for (int ni = 0; ni < 4; ni++) {
            const int r = row0 + m0w + mi * 16 + gr;
            const int c = col0 + n0w + ni * 8 + tc * 2;
            float2 bs = *(const float2*)(bias + c);
            float2 v0 = make_float2(acc[mi][ni][0] + bs.x, acc[mi][ni][1] + bs.y);
            float2 v1 = make_float2(acc[mi][ni][2] + bs.x, acc[mi][ni][3] + bs.y);
            *(float2*)(C + (size_t)r * N + c)       = v0;
            *(float2*)(C + (size_t)(r + 8) * N + c) = v1;
        }
    }
}

// ---------------- tensor-core windowed flash attention (tf32, unchanged) ----------------
#define QPAD 68
#define VPAD 72
__global__ void __launch_bounds__(128) attn_tc_kernel()
{
    __shared__ uint32_t Qs[64][QPAD];
    __shared__ uint32_t Ks[64][QPAD];
    __shared__ uint32_t Vs[64][VPAD];
    __shared__ uint32_t Ps[64][QPAD];

    const int q0  = blockIdx.x * 64;
    const int h   = blockIdx.y;
    const int b   = blockIdx.z;
    const int t   = threadIdx.x;
    const int wid = t >> 5;
    const int lane = t & 31;
    const int gr  = lane >> 2;
    const int tc  = lane & 3;

#pragma unroll
    for (int i = 0; i < 8; i++) {
        int lin = t + 128 * i;
        int row = lin >> 4;
        int c4  = (lin & 15) * 4;
        const float* src = g_qkv + (size_t)(b * S_LEN + q0 + row) * D3 + h * DHE + c4;
        float4 v = *(const float4*)src;
        *(uint4*)&Qs[row][c4] = make_uint4(f2tf(v.x * 0.125f), f2tf(v.y * 0.125f),
                                           f2tf(v.z * 0.125f), f2tf(v.w * 0.125f));
    }

    const int qr0 = q0 + wid * 16 + gr;
    const int qr1 = qr0 + 8;

    float m0 = -1e30f, m1 = -1e30f, l0 = 0.f, l1 = 0.f;
    float oacc[8][4];
#pragma unroll
    for (int nt = 0; nt < 8; nt++)
#pragma unroll
        for (int r = 0; r < 4; r++) oacc[nt][r] = 0.f;

    const int kstart = (q0 - WIN > 0) ? (q0 - WIN) : 0;
    const int kend   = (q0 + 64 + WIN < S_LEN) ? (q0 + 64 + WIN) : S_LEN;

    for (int kc = kstart; kc < kend; kc += 64) {
        __syncthreads();
#pragma unroll
        for (int i = 0; i < 8; i++) {
            int lin = t + 128 * i;
            int row = lin >> 4;
            int c4  = (lin & 15) * 4;
            const float* kp = g_qkv + (size_t)(b * S_LEN + kc + row) * D3 + D_DIM + h * DHE + c4;
            float4 kv = *(const float4*)kp;
            float4 vv = *(const float4*)(kp + D_DIM);
            *(uint4*)&Ks[row][c4] = make_uint4(f2tf(kv.x), f2tf(kv.y), f2tf(kv.z), f2tf(kv.w));
            *(uint4*)&Vs[row][c4] = make_uint4(f2tf(vv.x), f2tf(vv.y), f2tf(vv.z), f2tf(vv.w));
        }
        __syncthreads();

        float sacc[8][4];
#pragma unroll
        for (int nt = 0; nt < 8; nt++)
#pragma unroll
            for (int r = 0; r < 4; r++) sacc[nt][r] = 0.f;

#pragma unroll
        for (int ks = 0; ks < 8; ks++) {
            const int qrow = wid * 16 + gr;
            uint32_t af0 = Qs[qrow][ks * 8 + tc];
            uint32_t af1 = Qs[qrow + 8][ks * 8 + tc];
            uint32_t af2 = Qs[qrow][ks * 8 + tc + 4];
            uint32_t af3 = Qs[qrow + 8][ks * 8 + tc + 4];
#pragma unroll
            for (int nt = 0; nt < 8; nt++) {
                uint32_t b0 = Ks[nt * 8 + gr][ks * 8 + tc];
                uint32_t b1 = Ks[nt * 8 + gr][ks * 8 + tc + 4];
                mma_tf32(sacc[nt][0], sacc[nt][1], sacc[nt][2], sacc[nt][3],
                         af0, af1, af2, af3, b0, b1);
            }
        }

        float mx0 = m0, mx1 = m1;
#pragma unroll
        for (int nt = 0; nt < 8; nt++) {
            const int c = kc + nt * 8 + 2 * tc;
            if (c     < qr0 - WIN || c     > qr0 + WIN) sacc[nt][0] = -1e30f;
            if (c + 1 < qr0 - WIN || c + 1 > qr0 + WIN) sacc[nt][1] = -1e30f;
            if (c     < qr1 - WIN || c     > qr1 + WIN) sacc[nt][2] = -1e30f;
            if (c + 1 < qr1 - WIN || c + 1 > qr1 + WIN) sacc[nt][3] = -1e30f;
            mx0 = fmaxf(mx0, fmaxf(sacc[nt][0], sacc[nt][1]));
            mx1 = fmaxf(mx1, fmaxf(sacc[nt][2], sacc[nt][3]));
        }
        mx0 = fmaxf(mx0, __shfl_xor_sync(0xffffffffu, mx0, 1));
        mx0 = fmaxf(mx0, __shfl_xor_sync(0xffffffffu, mx0, 2));
        mx1 = fmaxf(mx1, __shfl_xor_sync(0xffffffffu, mx1, 1));
        mx1 = fmaxf(mx1, __shfl_xor_sync(0xffffffffu, mx1, 2));

        const float alpha0 = __expf(m0 - mx0);
        const float alpha1 = __expf(m1 - mx1);

        float ps0 = 0.f, ps1 = 0.f;
        const int prow = wid * 16 + gr;
#pragma unroll
        for (int nt = 0; nt < 8; nt++) {
            float p00 = __expf(sacc[nt][0] - mx0);
            float p01 = __expf(sacc[nt][1] - mx0);
            float p10 = __expf(sacc[nt][2] - mx1);
            float p11 = __expf(sacc[nt][3] - mx1);
            ps0 += p00 + p01;
            ps1 += p10 + p11;
            *(uint2*)&Ps[prow][nt * 8 + 2 * tc]     = make_uint2(f2tf(p00), f2tf(p01));
            *(uint2*)&Ps[prow + 8][nt * 8 + 2 * tc] = make_uint2(f2tf(p10), f2tf(p11));
        }
        ps0 += __shfl_xor_sync(0xffffffffu, ps0, 1);
        ps0 += __shfl_xor_sync(0xffffffffu, ps0, 2);
        ps1 += __shfl_xor_sync(0xffffffffu, ps1, 1);
        ps1 += __shfl_xor_sync(0xffffffffu, ps1, 2);

        l0 = l0 * alpha0 + ps0;  m0 = mx0;
        l1 = l1 * alpha1 + ps1;  m1 = mx1;

#pragma unroll
        for (int nt = 0; nt < 8; nt++) {
            oacc[nt][0] *= alpha0; oacc[nt][1] *= alpha0;
            oacc[nt][2] *= alpha1; oacc[nt][3] *= alpha1;
        }

        __syncwarp();

#pragma unroll
        for (int ks = 0; ks < 8; ks++) {
            uint32_t af0 = Ps[prow][ks * 8 + tc];
            uint32_t af1 = Ps[prow + 8][ks * 8 + tc];
            uint32_t af2 = Ps[prow][ks * 8 + tc + 4];
            uint32_t af3 = Ps[prow + 8][ks * 8 + tc + 4];
#pragma unroll
            for (int nt = 0; nt < 8; nt++) {
                uint32_t b0 = Vs[ks * 8 + tc][nt * 8 + gr];
                uint32_t b1 = Vs[ks * 8 + tc + 4][nt * 8 + gr];
                mma_tf32(oacc[nt][0], oacc[nt][1], oacc[nt][2], oacc[nt][3],
                         af0, af1, af2, af3, b0, b1);
            }
        }
    }

    const float inv0 = 1.0f / l0;
    const float inv1 = 1.0f / l1;
    const size_t row0g = (size_t)(b * S_LEN) + qr0;
#pragma unroll
    for (int nt = 0; nt < 8; nt++) {
        const int col = h * DHE + nt * 8 + 2 * tc;
        *(uint32_t*)(g_attn_h + row0g * D_DIM + col) =
            f22h2(oacc[nt][0] * inv0, oacc[nt][1] * inv0);
        *(uint32_t*)(g_attn_h + (row0g + 8) * D_DIM + col) =
            f22h2(oacc[nt][2] * inv1, oacc[nt][3] * inv1);
    }
}

// ---------------- fused double LayerNorm ----------------
__global__ void __launch_bounds__(256) fused_ln2_kernel(
    const float* __restrict__ X, const float* __restrict__ AO,
    const float* __restrict__ g1, const float* __restrict__ b1,
    const float* __restrict__ XW,
    const float* __restrict__ g2, const float* __restrict__ b2,
    float* __restrict__ out)
{
    __shared__ float red[8];
    const int row = blockIdx.x;
    const int t   = threadIdx.x;
    const float invD = 1.f / (float)D_DIM;

    float4 a = *(const float4*)(X  + (size_t)row * D_DIM + t * 4);
    float4 b = *(const float4*)(AO + (size_t)row * D_DIM + t * 4);
    float4 v = make_float4(a.x + b.x, a.y + b.y, a.z + b.z, a.w + b.w);

    float s = v.x + v.y + v.z + v.w;
#pragma unroll
    for (int o = 16; o; o >>= 1) s += __shfl_xor_sync(0xffffffffu, s, o);
    if ((t & 31) == 0) red[t >> 5] = s;
    __syncthreads();
    float tot = 0.f;
#pragma unroll
    for (int i = 0; i < 8; i++) tot += red[i];
    const float mu1 = tot * invD;
    __syncthreads();

    float dx = v.x - mu1, dy = v.y - mu1, dz = v.z - mu1, dw = v.w - mu1;
    float s2 = dx * dx + dy * dy + dz * dz + dw * dw;
#pragma unroll
    for (int o = 16; o; o >>= 1) s2 += __shfl_xor_sync(0xffffffffu, s2, o);
    if ((t & 31) == 0) red[t >> 5] = s2;
    __syncthreads();
    float tot2 = 0.f;
#pragma unroll
    for (int i = 0; i < 8; i++) tot2 += red[i];
    const float inv1v = rsqrtf(tot2 * invD + 1e-5f);
    __syncthreads();

    float4 gg = *(const float4*)(g1 + t * 4);
    float4 bb = *(const float4*)(b1 + t * 4);
    float4 w  = *(const float4*)(XW + (size_t)row * D_DIM + t * 4);
    float4 v2 = make_float4(dx * inv1v * gg.x + bb.x + w.x,
                            dy * inv1v * gg.y + bb.y + w.y,
                            dz * inv1v * gg.z + bb.z + w.z,
                            dw * inv1v * gg.w + bb.w + w.w);

    float s3 = v2.x + v2.y + v2.z + v2.w;
#pragma unroll
    for (int o = 16; o; o >>= 1) s3 += __shfl_xor_sync(0xffffffffu, s3, o);
    if ((t & 31) == 0) red[t >> 5] = s3;
    __syncthreads();
    float tot3 = 0.f;
#pragma unroll
    for (int i = 0; i < 8; i++) tot3 += red[i];
    const float mu2 = tot3 * invD;
    __syncthreads();

    float ex = v2.x - mu2, ey = v2.y - mu2, ez = v2.z - mu2, ew = v2.w - mu2;
    float s4 = ex * ex + ey * ey + ez * ez + ew * ew;
#pragma unroll
    for (int o = 16; o; o >>= 1) s4 += __shfl_xor_sync(0xffffffffu, s4, o);
    if ((t & 31) == 0) red[t >> 5] = s4;
    __syncthreads();
    float tot4 = 0.f;
#pragma unroll
    for (int i = 0; i < 8; i++) tot4 += red[i];
    const float inv2v = rsqrtf(tot4 * invD + 1e-5f);

    float4 g2v = *(const float4*)(g2 + t * 4);
    float4 b2v = *(const float4*)(b2 + t * 4);
    float4 o4 = make_float4(ex * inv2v * g2v.x + b2v.x, ey * inv2v * g2v.y + b2v.y,
                            ez * inv2v * g2v.z + b2v.z, ew * inv2v * g2v.w + b2v.w);
    *(float4*)(out + (size_t)row * D_DIM + t * 4) = o4;
}

// ---------------- launcher ----------------
extern "C" void kernel_launch(void* const* d_in, const int* in_sizes, int n_in,
                              void* d_out, int out_size)
{
    const float* x     = (const float*)d_in[0];
    const float* in_w  = (const float*)d_in[1];
    const float* in_b  = (const float*)d_in[2];
    const float* out_w = (const float*)d_in[3];
    const float* out_b = (const float*)d_in[4];
    const float* ln1g  = (const float*)d_in[5];
    const float* ln1b  = (const float*)d_in[6];
    const float* wr    = (const float*)d_in[7];
    const float* wi    = (const float*)d_in[8];
    const float* ln2g  = (const float*)d_in[9];
    const float* ln2b  = (const float*)d_in[10];
    float* out = (float*)d_out;

    float *qkv, *attnout, *xwave;
    __half *xh, *wh_in, *wh_out, *attn_h;
    cudaGetSymbolAddress((void**)&qkv,     g_qkv);
    cudaGetSymbolAddress((void**)&attnout, g_attnout);
    cudaGetSymbolAddress((void**)&xwave,   g_xwave);
    cudaGetSymbolAddress((void**)&xh,      g_xh);
    cudaGetSymbolAddress((void**)&wh_in,   g_wh_in);
    cudaGetSymbolAddress((void**)&wh_out,  g_wh_out);
    cudaGetSymbolAddress((void**)&attn_h,  g_attn_h);

    // converts (bandwidth-bound, tiny)
    conv_f2h<<<(NTOK * D_DIM / 4 + 255) / 256, 256>>>(x, xh, NTOK * D_DIM);
    conv_f2h<<<(D3 * D_DIM / 4 + 255) / 256, 256>>>(in_w, wh_in, D3 * D_DIM);
    conv_f2h<<<(D_DIM * D_DIM / 4 + 255) / 256, 256>>>(out_w, wh_out, D_DIM * D_DIM);

    // QKV GEMM + spectral FFT in ONE launch, block roles interleaved 3:4
    fused_qkv_spec<<<TOTAL_BLOCKS, 256>>>(xh, wh_in, in_b, qkv,
                                          x, wr, wi, xwave);

    // windowed flash attention (tf32 mma.sync; writes half attn)
    attn_tc_kernel<<<dim3(S_LEN / 64, NH, B_SZ), 128>>>();

    // output projection (fp16)
    gemm_fp16_pipe<<<dim3(D_DIM / 128, NTOK / 128), 256>>>(attn_h, wh_out, out_b, attnout,
                                                           NTOK, D_DIM, D_DIM);

    // out = LN2( LN1(x + attnout) + xwave )  -- fused
    fused_ln2_kernel<<<NTOK, 256>>>(x, attnout, ln1g, ln1b, xwave, ln2g, ln2b, out);
}

// round 16
// speedup vs baseline: 1.1146x; 1.1146x over previous
#include <cuda_runtime.h>
#include <cuda_fp16.h>
#include <math.h>
#include <stdint.h>

#define S_LEN 2048
#define D_DIM 1024
#define B_SZ  2
#define NH    16
#define DHE   64
#define WIN   128
#define NTOK  (B_SZ * S_LEN)   // 4096
#define D3    (3 * D_DIM)      // 3072

#define SMAP(i) ((i) + ((i) >> 4))

// ---------------- scratch ----------------
__device__ __half g_qkv_h[(size_t)NTOK * D3];        // QKV in half
__device__ __half g_attn_h[(size_t)NTOK * D_DIM];
__device__ float  g_attnout[(size_t)NTOK * D_DIM];
__device__ float  g_xwave[(size_t)NTOK * D_DIM];
__device__ __half g_xh[(size_t)NTOK * D_DIM];
__device__ __half g_wh_in[(size_t)D3 * D_DIM];
__device__ __half g_wh_out[(size_t)D_DIM * D_DIM];

// ---------------- helpers ----------------
__device__ __forceinline__ uint32_t smem_u32(const void* p) {
    uint32_t a;
    asm("{ .reg .u64 t; cvta.to.shared.u64 t, %1; cvt.u32.u64 %0, t; }" : "=r"(a) : "l"(p));
    return a;
}
__device__ __forceinline__ void cpasync16(uint32_t dst, const void* src) {
    asm volatile("cp.async.ca.shared.global [%0], [%1], 16;" :: "r"(dst), "l"(src));
}
#define CP_COMMIT() asm volatile("cp.async.commit_group;" ::: "memory")
#define CP_WAIT1()  asm volatile("cp.async.wait_group 1;" ::: "memory")

__device__ __forceinline__ uint32_t f22h2(float a, float b) {
    __half2 h = __floats2half2_rn(a, b);
    return *(uint32_t*)&h;
}
__device__ __forceinline__ uint32_t f2tf(float f) {
    uint32_t u;
    asm("cvt.rna.tf32.f32 %0, %1;" : "=r"(u) : "f"(f));
    return u;
}
__device__ __forceinline__ void mma_fp16(
    float& c0, float& c1, float& c2, float& c3,
    uint32_t a0, uint32_t a1, uint32_t a2, uint32_t a3,
    uint32_t b0, uint32_t b1)
{
    asm volatile(
        "mma.sync.aligned.m16n8k16.row.col.f32.f16.f16.f32 "
        "{%0,%1,%2,%3}, {%4,%5,%6,%7}, {%8,%9}, {%0,%1,%2,%3};\n"
        : "+f"(c0), "+f"(c1), "+f"(c2), "+f"(c3)
        : "r"(a0), "r"(a1), "r"(a2), "r"(a3), "r"(b0), "r"(b1));
}
__device__ __forceinline__ void mma_tf32(
    float& c0, float& c1, float& c2, float& c3,
    uint32_t a0, uint32_t a1, uint32_t a2, uint32_t a3,
    uint32_t b0, uint32_t b1)
{
    asm volatile(
        "mma.sync.aligned.m16n8k8.row.col.f32.tf32.tf32.f32 "
        "{%0,%1,%2,%3}, {%4,%5,%6,%7}, {%8,%9}, {%0,%1,%2,%3};\n"
        : "+f"(c0), "+f"(c1), "+f"(c2), "+f"(c3)
        : "r"(a0), "r"(a1), "r"(a2), "r"(a3), "r"(b0), "r"(b1));
}

// ---------------- f32 -> f16 convert ----------------
__global__ void __launch_bounds__(256) conv_f2h(const float* __restrict__ src,
                                               __half* __restrict__ dst, int n)
{
    int i = (blockIdx.x * 256 + threadIdx.x) * 4;
    if (i < n) {
        float4 v = *(const float4*)(src + i);
        *(uint2*)(dst + i) = make_uint2(f22h2(v.x, v.y), f22h2(v.z, v.w));
    }
}

// ---------------- complex helpers ----------------
__device__ __forceinline__ float2 cmul(float2 a, float2 b) {
    return make_float2(a.x * b.x - a.y * b.y, a.x * b.y + a.y * b.x);
}
__device__ __forceinline__ float2 cadd(float2 a, float2 b) {
    return make_float2(a.x + b.x, a.y + b.y);
}
__device__ __forceinline__ float2 csub(float2 a, float2 b) {
    return make_float2(a.x - b.x, a.y - b.y);
}

// fused radix-8 Stockham (validated round 13)
template<int SIGN>
__device__ __forceinline__ void fft2048_r8(float2*& cur, float2*& oth)
{
    const float C8 = 0.70710678118654752f;
    const float SG = (float)SIGN;
#pragma unroll
    for (int st = 0; st < 3; st++) {
        const int ls = st * 3;
        const int ss = 1 << ls;
        const int n  = 2048 >> ls;
        const float fn = (2.0f * 3.14159265358979f * SG) / (float)n;
        const int idx = threadIdx.x;
        const int p = idx >> ls;
        const int q = idx & (ss - 1);

        float2 x0 = cur[SMAP(idx)];
        float2 x1 = cur[SMAP(idx + 256)];
        float2 x2 = cur[SMAP(idx + 512)];
        float2 x3 = cur[SMAP(idx + 768)];
        float2 x4 = cur[SMAP(idx + 1024)];
        float2 x5 = cur[SMAP(idx + 1280)];
        float2 x6 = cur[SMAP(idx + 1536)];
        float2 x7 = cur[SMAP(idx + 1792)];

        float2 es = cadd(x0, x4), ed = csub(x0, x4);
        float2 fs = cadd(x2, x6), fd = csub(x2, x6);
        float2 E0 = cadd(es, fs);
        float2 E2 = csub(es, fs);
        float2 E1 = make_float2(ed.x - SG * fd.y, ed.y + SG * fd.x);
        float2 E3 = make_float2(ed.x + SG * fd.y, ed.y - SG * fd.x);
        float2 os = cadd(x1, x5), od = csub(x1, x5);
        float2 gs = cadd(x3, x7), gd = csub(x3, x7);
        float2 O0 = cadd(os, gs);
        float2 O2 = csub(os, gs);
        float2 O1 = make_float2(od.x - SG * gd.y, od.y + SG * gd.x);
        float2 O3 = make_float2(od.x + SG * gd.y, od.y - SG * gd.x);
        float2 t0 = O0;
        float2 t1 = make_float2(C8 * (O1.x - SG * O1.y), C8 * (SG * O1.x + O1.y));
        float2 t2 = make_float2(-SG * O2.y, SG * O2.x);
        float2 t3 = make_float2(C8 * (-O3.x - SG * O3.y), C8 * (SG * O3.x - O3.y));

        float2 X0 = cadd(E0, t0), X4 = csub(E0, t0);
        float2 X1 = cadd(E1, t1), X5 = csub(E1, t1);
        float2 X2 = cadd(E2, t2), X6 = csub(E2, t2);
        float2 X3 = cadd(E3, t3), X7 = csub(E3, t3);

        float sn, cs;
        __sincosf(fn * (float)p, &sn, &cs);
        const float2 w1 = make_float2(cs, sn);
        const float2 w2 = cmul(w1, w1);
        const float2 w3 = cmul(w1, w2);
        const float2 w4 = cmul(w2, w2);
        const float2 w5 = cmul(w2, w3);
        const float2 w6 = cmul(w3, w3);
        const float2 w7 = cmul(w3, w4);

        const int ob = q + 8 * ss * p;
        oth[SMAP(ob)]          = X0;
        oth[SMAP(ob + ss)]     = cmul(X1, w1);
        oth[SMAP(ob + 2 * ss)] = cmul(X2, w2);
        oth[SMAP(ob + 3 * ss)] = cmul(X3, w3);
        oth[SMAP(ob + 4 * ss)] = cmul(X4, w4);
        oth[SMAP(ob + 5 * ss)] = cmul(X5, w5);
        oth[SMAP(ob + 6 * ss)] = cmul(X6, w6);
        oth[SMAP(ob + 7 * ss)] = cmul(X7, w7);

        __syncthreads();
        float2* tmp = cur; cur = oth; oth = tmp;
    }
#pragma unroll
    for (int ii = 0; ii < 2; ii++) {
        const int qq = threadIdx.x + 256 * ii;
        float2 x0 = cur[SMAP(qq)];
        float2 x1 = cur[SMAP(qq + 512)];
        float2 x2 = cur[SMAP(qq + 1024)];
        float2 x3 = cur[SMAP(qq + 1536)];
        float2 a0 = cadd(x0, x2), a1 = csub(x0, x2);
        float2 b0 = cadd(x1, x3), u = csub(x1, x3);
        float2 b1 = make_float2(-SG * u.y, SG * u.x);
        oth[SMAP(qq)]        = cadd(a0, b0);
        oth[SMAP(qq + 512)]  = cadd(a1, b1);
        oth[SMAP(qq + 1024)] = csub(a0, b0);
        oth[SMAP(qq + 1536)] = csub(a1, b1);
    }
    __syncthreads();
    { float2* tmp = cur; cur = oth; oth = tmp; }
}

// ---------------- fused QKV GEMM + spectral (grouped ordering, round-14 style) ----------------
#define LDP 20
#define STG 3
#define GEMM_BX (D3 / 128)                     // 24
#define GEMM_BLOCKS (GEMM_BX * (NTOK / 128))   // 768

union SmemU {
    struct { uint32_t As2[STG][128][LDP]; uint32_t Ws2[STG][128][LDP]; } g;  // 61440 B
    struct { float2 bufA[2176]; float2 bufB[2176]; } s;                      // 34816 B
};

__global__ void __launch_bounds__(256, 2) fused_qkv_spec(
    const __half* __restrict__ A, const __half* __restrict__ W,
    const float* __restrict__ bias, __half* __restrict__ C,
    const float* __restrict__ x, const float* __restrict__ wr,
    const float* __restrict__ wi, float* __restrict__ xwave)
{
    __shared__ SmemU u;
    const int t = threadIdx.x;

    if (blockIdx.x < GEMM_BLOCKS) {
        // ================= QKV GEMM path (M=NTOK, N=D3, K=D_DIM) -> half output =====
        const int  N = D3, K = D_DIM;
        const int row0 = (blockIdx.x / GEMM_BX) * 128;
        const int col0 = (blockIdx.x % GEMM_BX) * 128;
        const int warp = t >> 5;
        const int lane = t & 31;
        const int gr   = lane >> 2;
        const int tc   = lane & 3;
        const int m0w  = (warp >> 2) * 64;
        const int n0w  = (warp & 3) * 32;

        const int r0c = t >> 2;          const int c0c = t & 3;
        const int r1c = (t + 256) >> 2;  const int c1c = (t + 256) & 3;

        const __half* Ar0 = A + (size_t)(row0 + r0c) * K + c0c * 8;
        const __half* Ar1 = A + (size_t)(row0 + r1c) * K + c1c * 8;
        const __half* Wr0 = W + (size_t)(col0 + r0c) * K + c0c * 8;
        const __half* Wr1 = W + (size_t)(col0 + r1c) * K + c1c * 8;

        float acc[4][4][4];
#pragma unroll
        for (int mi = 0; mi < 4; mi++)
#pragma unroll
            for (int ni = 0; ni < 4; ni++)
#pragma unroll
                for (int r = 0; r < 4; r++) acc[mi][ni][r] = 0.f;

        const int ntiles = K >> 5;

#pragma unroll
        for (int s = 0; s < 2; s++) {
            const int k0 = s << 5;
            cpasync16(smem_u32(&u.g.As2[s][r0c][c0c * 4]), Ar0 + k0);
            cpasync16(smem_u32(&u.g.As2[s][r1c][c1c * 4]), Ar1 + k0);
            cpasync16(smem_u32(&u.g.Ws2[s][r0c][c0c * 4]), Wr0 + k0);
            cpasync16(smem_u32(&u.g.Ws2[s][r1c][c1c * 4]), Wr1 + k0);
            CP_COMMIT();
        }

        int cb = 0, nst = 2;
        for (int kt = 0; kt < ntiles; kt++) {
            CP_WAIT1();
            __syncthreads();

            if (kt + 2 < ntiles) {
                const int k0 = (kt + 2) << 5;
                cpasync16(smem_u32(&u.g.As2[nst][r0c][c0c * 4]), Ar0 + k0);
                cpasync16(smem_u32(&u.g.As2[nst][r1c][c1c * 4]), Ar1 + k0);
                cpasync16(smem_u32(&u.g.Ws2[nst][r0c][c0c * 4]), Wr0 + k0);
                cpasync16(smem_u32(&u.g.Ws2[nst][r1c][c1c * 4]), Wr1 + k0);
            }
            CP_COMMIT();

#pragma unroll
            for (int kk = 0; kk < 2; kk++) {
                uint32_t af[4][4];
#pragma unroll
                for (int mi = 0; mi < 4; mi++) {
                    const int br = m0w + mi * 16;
                    af[mi][0] = u.g.As2[cb][br + gr][kk * 8 + tc];
                    af[mi][1] = u.g.As2[cb][br + gr + 8][kk * 8 + tc];
                    af[mi][2] = u.g.As2[cb][br + gr][kk * 8 + tc + 4];
                    af[mi][3] = u.g.As2[cb][br + gr + 8][kk * 8 + tc + 4];
                }
                uint32_t bf[4][2];
#pragma unroll
                for (int ni = 0; ni < 4; ni++) {
                    const int bn = n0w + ni * 8 + gr;
                    bf[ni][0] = u.g.Ws2[cb][bn][kk * 8 + tc];
                    bf[ni][1] = u.g.Ws2[cb][bn][kk * 8 + tc + 4];
                }
#pragma unroll
                for (int mi = 0; mi < 4; mi++)
#pragma unroll
                    for (int ni = 0; ni < 4; ni++)
                        mma_fp16(acc[mi][ni][0], acc[mi][ni][1], acc[mi][ni][2], acc[mi][ni][3],
                                 af[mi][0], af[mi][1], af[mi][2], af[mi][3],
                                 bf[ni][0], bf[ni][1]);
            }

            cb  = (cb  + 1) % STG;
            nst = (nst + 1) % STG;
        }

        // epilogue: half output
#pragma unroll
        for (int mi = 0; mi < 4; mi++) {
#pragma unroll
            for (int ni = 0; ni < 4; ni++) {
                const int r = row0 + m0w + mi * 16 + gr;
                const int c = col0 + n0w + ni * 8 + tc * 2;
                float2 bs = *(const float2*)(bias + c);
                *(uint32_t*)(C + (size_t)r * N + c) =
                    f22h2(acc[mi][ni][0] + bs.x, acc[mi][ni][1] + bs.y);
                *(uint32_t*)(C + (size_t)(r + 8) * N + c) =
                    f22h2(acc[mi][ni][2] + bs.x, acc[mi][ni][3] + bs.y);
            }
        }
    } else {
        // ================= spectral path =================
        const int sid = blockIdx.x - GEMM_BLOCKS;
        const int d0 = (sid & 511) * 2;
        const int b  = sid >> 9;

        float2* bufA = u.s.bufA;
        float2* bufB = u.s.bufB;

        const float* xp = x + (size_t)b * S_LEN * D_DIM + d0;
        for (int s = t; s < 2048; s += 256)
            bufA[SMAP(s)] = *(const float2*)(xp + (size_t)s * D_DIM);
        __syncthreads();

        float2* cur = bufA;
        float2* oth = bufB;
        fft2048_r8<-1>(cur, oth);

        for (int k = t; k < 2048; k += 256) {
            const int km = (2048 - k) & 2047;
            float2 Zk = cur[SMAP(k)];
            float2 Zm = cur[SMAP(km)];
            float2 Av = make_float2(0.5f * (Zk.x + Zm.x), 0.5f * (Zk.y - Zm.y));
            float2 Bc = make_float2(0.5f * (Zk.y + Zm.y), -0.5f * (Zk.x - Zm.x));
            const int   kf  = (k <= 1024) ? k : 2048 - k;
            const float sgn = (k <= 1024) ? 1.f : -1.f;
            float2 wrp = *(const float2*)(wr + (size_t)kf * D_DIM + d0);
            float2 wip = *(const float2*)(wi + (size_t)kf * D_DIM + d0);
            float2 c1 = make_float2(wrp.x, sgn * wip.x);
            float2 c2 = make_float2(wrp.y, sgn * wip.y);
            if (k == 0 || k == 1024) { c1.y = 0.f; c2.y = 0.f; }
            float2 Y1 = cmul(Av, c1);
            float2 Y2 = cmul(Bc, c2);
            oth[SMAP(k)] = make_float2(Y1.x - Y2.y, Y1.y + Y2.x);
        }
        __syncthreads();
        { float2* tmp = cur; cur = oth; oth = tmp; }

        fft2048_r8<1>(cur, oth);

        float* dst = xwave + (size_t)b * S_LEN * D_DIM + d0;
        const float invn = 1.0f / 2048.0f;
        for (int s = t; s < 2048; s += 256) {
            float2 r = cur[SMAP(s)];
            *(float2*)(dst + (size_t)s * D_DIM) = make_float2(r.x * invn, r.y * invn);
        }
    }
}

// ---------------- fp16 GEMM, 3-stage cp.async pipeline (out-proj, f32 out) ----------------
__global__ void __launch_bounds__(256, 2) gemm_fp16_pipe(
    const __half* __restrict__ A, const __half* __restrict__ W,
    const float* __restrict__ bias, float* __restrict__ C,
    int M, int N, int K)
{
    __shared__ uint32_t As2[STG][128][LDP];
    __shared__ uint32_t Ws2[STG][128][LDP];

    const int row0 = blockIdx.y * 128;
    const int col0 = blockIdx.x * 128;
    const int t    = threadIdx.x;
    const int warp = t >> 5;
    const int lane = t & 31;
    const int gr   = lane >> 2;
    const int tc   = lane & 3;
    const int m0w  = (warp >> 2) * 64;
    const int n0w  = (warp & 3) * 32;

    const int r0c = t >> 2;          const int c0c = t & 3;
    const int r1c = (t + 256) >> 2;  const int c1c = (t + 256) & 3;

    const __half* Ar0 = A + (size_t)(row0 + r0c) * K + c0c * 8;
    const __half* Ar1 = A + (size_t)(row0 + r1c) * K + c1c * 8;
    const __half* Wr0 = W + (size_t)(col0 + r0c) * K + c0c * 8;
    const __half* Wr1 = W + (size_t)(col0 + r1c) * K + c1c * 8;

    float acc[4][4][4];
#pragma unroll
    for (int mi = 0; mi < 4; mi++)
#pragma unroll
        for (int ni = 0; ni < 4; ni++)
#pragma unroll
            for (int r = 0; r < 4; r++) acc[mi][ni][r] = 0.f;

    const int ntiles = K >> 5;

#pragma unroll
    for (int s = 0; s < 2; s++) {
        const int k0 = s << 5;
        cpasync16(smem_u32(&As2[s][r0c][c0c * 4]), Ar0 + k0);
        cpasync16(smem_u32(&As2[s][r1c][c1c * 4]), Ar1 + k0);
        cpasync16(smem_u32(&Ws2[s][r0c][c0c * 4]), Wr0 + k0);
        cpasync16(smem_u32(&Ws2[s][r1c][c1c * 4]), Wr1 + k0);
        CP_COMMIT();
    }

    int cb = 0, nst = 2;
    for (int kt = 0; kt < ntiles; kt++) {
        CP_WAIT1();
        __syncthreads();

        if (kt + 2 < ntiles) {
            const int k0 = (kt + 2) << 5;
            cpasync16(smem_u32(&As2[nst][r0c][c0c * 4]), Ar0 + k0);
            cpasync16(smem_u32(&As2[nst][r1c][c1c * 4]), Ar1 + k0);
            cpasync16(smem_u32(&Ws2[nst][r0c][c0c * 4]), Wr0 + k0);
            cpasync16(smem_u32(&Ws2[nst][r1c][c1c * 4]), Wr1 + k0);
        }
        CP_COMMIT();

#pragma unroll
        for (int kk = 0; kk < 2; kk++) {
            uint32_t af[4][4];
#pragma unroll
            for (int mi = 0; mi < 4; mi++) {
                const int br = m0w + mi * 16;
                af[mi][0] = As2[cb][br + gr][kk * 8 + tc];
                af[mi][1] = As2[cb][br + gr + 8][kk * 8 + tc];
                af[mi][2] = As2[cb][br + gr][kk * 8 + tc + 4];
                af[mi][3] = As2[cb][br + gr + 8][kk * 8 + tc + 4];
            }
            uint32_t bf[4][2];
#pragma unroll
            for (int ni = 0; ni < 4; ni++) {
                const int bn = n0w + ni * 8 + gr;
                bf[ni][0] = Ws2[cb][bn][kk * 8 + tc];
                bf[ni][1] = Ws2[cb][bn][kk * 8 + tc + 4];
            }
#pragma unroll
            for (int mi = 0; mi < 4; mi++)
#pragma unroll
                for (int ni = 0; ni < 4; ni++)
                    mma_fp16(acc[mi][ni][0], acc[mi][ni][1], acc[mi][ni][2], acc[mi][ni][3],
                             af[mi][0], af[mi][1], af[mi][2], af[mi][3],
                             bf[ni][0], bf[ni][1]);
        }

        cb  = (cb  + 1) % STG;
        nst = (nst + 1) % STG;
    }

#pragma unroll
    for (int mi = 0; mi < 4; mi++) {
#pragma unroll
        for (int ni = 0; ni < 4; ni++) {
            const int r = row0 + m0w + mi * 16 + gr;
            const int c = col0 + n0w + ni * 8 + tc * 2;
            float2 bs = *(const float2*)(bias + c);
            float2 v0 = make_float2(acc[mi][ni][0] + bs.x, acc[mi][ni][1] + bs.y);
            float2 v1 = make_float2(acc[mi][ni][2] + bs.x, acc[mi][ni][3] + bs.y);
            *(float2*)(C + (size_t)r * N + c)       = v0;
            *(float2*)(C + (size_t)(r + 8) * N + c) = v1;
        }
    }
}

// ---------------- windowed flash attention: fp16 QK^T + tf32 PV ----------------
#define KPAD 36       // Q/K smem: 32 u32 (64 halves) per row + pad
#define VPAD 72
#define PPAD 68
__global__ void __launch_bounds__(128) attn_tc_kernel()
{
    __shared__ uint32_t Qs[64][KPAD];   // half2-packed, dh pairs
    __shared__ uint32_t Ks[64][KPAD];   // half2-packed
    __shared__ uint32_t Vs[64][VPAD];   // tf32
    __shared__ uint32_t Ps[64][PPAD];   // tf32

    const int q0  = blockIdx.x * 64;
    const int h   = blockIdx.y;
    const int b   = blockIdx.z;
    const int t   = threadIdx.x;
    const int wid = t >> 5;
    const int lane = t & 31;
    const int gr  = lane >> 2;
    const int tc  = lane & 3;

    const __half2 qscale = __float2half2_rn(0.125f);

    // load Q tile (half, scaled): 1024 uint2 slots; slot s -> row = s>>4, cu = (s&15)*2
#pragma unroll
    for (int i = 0; i < 8; i++) {
        int s   = t + 128 * i;
        int row = s >> 4;
        int cu  = (s & 15) * 2;     // u32 offset within row (2 u32 = 4 halves)
        const __half* src = g_qkv_h + (size_t)(b * S_LEN + q0 + row) * D3 + h * DHE + cu * 2;
        uint2 v = *(const uint2*)src;
        __half2 h0 = __hmul2(*(__half2*)&v.x, qscale);
        __half2 h1 = __hmul2(*(__half2*)&v.y, qscale);
        *(uint2*)&Qs[row][cu] = make_uint2(*(uint32_t*)&h0, *(uint32_t*)&h1);
    }

    const int qr0 = q0 + wid * 16 + gr;
    const int qr1 = qr0 + 8;

    float m0 = -1e30f, m1 = -1e30f, l0 = 0.f, l1 = 0.f;
    float oacc[8][4];
#pragma unroll
    for (int nt = 0; nt < 8; nt++)
#pragma unroll
        for (int r = 0; r < 4; r++) oacc[nt][r] = 0.f;

    const int kstart = (q0 - WIN > 0) ? (q0 - WIN) : 0;
    const int kend   = (q0 + 64 + WIN < S_LEN) ? (q0 + 64 + WIN) : S_LEN;

    for (int kc = kstart; kc < kend; kc += 64) {
        __syncthreads();
        // load K (half) and V (half -> tf32)
#pragma unroll
        for (int i = 0; i < 8; i++) {
            int s   = t + 128 * i;
            int row = s >> 4;
            int cu  = (s & 15) * 2;
            const __half* kp = g_qkv_h + (size_t)(b * S_LEN + kc + row) * D3 + D_DIM + h * DHE + cu * 2;
            uint2 kv = *(const uint2*)kp;
            *(uint2*)&Ks[row][cu] = kv;
            uint2 vv = *(const uint2*)(kp + D_DIM);
            float2 f0 = __half22float2(*(__half2*)&vv.x);
            float2 f1 = __half22float2(*(__half2*)&vv.y);
            const int dh0 = (s & 15) * 4;
            *(uint4*)&Vs[row][dh0] = make_uint4(f2tf(f0.x), f2tf(f0.y), f2tf(f1.x), f2tf(f1.y));
        }
        __syncthreads();

        // S = Q @ K^T  (fp16, 4 k16 steps over dh=64)
        float sacc[8][4];
#pragma unroll
        for (int nt = 0; nt < 8; nt++)
#pragma unroll
            for (int r = 0; r < 4; r++) sacc[nt][r] = 0.f;

#pragma unroll
        for (int ks = 0; ks < 4; ks++) {
            const int qrow = wid * 16 + gr;
            uint32_t af0 = Qs[qrow][ks * 8 + tc];
            uint32_t af1 = Qs[qrow + 8][ks * 8 + tc];
            uint32_t af2 = Qs[qrow][ks * 8 + tc + 4];
            uint32_t af3 = Qs[qrow + 8][ks * 8 + tc + 4];
#pragma unroll
            for (int nt = 0; nt < 8; nt++) {
                uint32_t b0 = Ks[nt * 8 + gr][ks * 8 + tc];
                uint32_t b1 = Ks[nt * 8 + gr][ks * 8 + tc + 4];
                mma_fp16(sacc[nt][0], sacc[nt][1], sacc[nt][2], sacc[nt][3],
                         af0, af1, af2, af3, b0, b1);
            }
        }

        float mx0 = m0, mx1 = m1;
#pragma unroll
        for (int nt = 0; nt < 8; nt++) {
            const int c = kc + nt * 8 + 2 * tc;
            if (c     < qr0 - WIN || c     > qr0 + WIN) sacc[nt][0] = -1e30f;
            if (c + 1 < qr0 - WIN || c + 1 > qr0 + WIN) sacc[nt][1] = -1e30f;
            if (c     < qr1 - WIN || c     > qr1 + WIN) sacc[nt][2] = -1e30f;
            if (c + 1 < qr1 - WIN || c + 1 > qr1 + WIN) sacc[nt][3] = -1e30f;
            mx0 = fmaxf(mx0, fmaxf(sacc[nt][0], sacc[nt][1]));
            mx1 = fmaxf(mx1, fmaxf(sacc[nt][2], sacc[nt][3]));
        }
        mx0 = fmaxf(mx0, __shfl_xor_sync(0xffffffffu, mx0, 1));
        mx0 = fmaxf(mx0, __shfl_xor_sync(0xffffffffu, mx0, 2));
        mx1 = fmaxf(mx1, __shfl_xor_sync(0xffffffffu, mx1, 1));
        mx1 = fmaxf(mx1, __shfl_xor_sync(0xffffffffu, mx1, 2));

        const float alpha0 = __expf(m0 - mx0);
        const float alpha1 = __expf(m1 - mx1);

        float ps0 = 0.f, ps1 = 0.f;
        const int prow = wid * 16 + gr;
#pragma unroll
        for (int nt = 0; nt < 8; nt++) {
            float p00 = __expf(sacc[nt][0] - mx0);
            float p01 = __expf(sacc[nt][1] - mx0);
            float p10 = __expf(sacc[nt][2] - mx1);
            float p11 = __expf(sacc[nt][3] - mx1);
            ps0 += p00 + p01;
            ps1 += p10 + p11;
            *(uint2*)&Ps[prow][nt * 8 + 2 * tc]     = make_uint2(f2tf(p00), f2tf(p01));
            *(uint2*)&Ps[prow + 8][nt * 8 + 2 * tc] = make_uint2(f2tf(p10), f2tf(p11));
        }
        ps0 += __shfl_xor_sync(0xffffffffu, ps0, 1);
        ps0 += __shfl_xor_sync(0xffffffffu, ps0, 2);
        ps1 += __shfl_xor_sync(0xffffffffu, ps1, 1);
        ps1 += __shfl_xor_sync(0xffffffffu, ps1, 2);

        l0 = l0 * alpha0 + ps0;  m0 = mx0;
        l1 = l1 * alpha1 + ps1;  m1 = mx1;

#pragma unroll
        for (int nt = 0; nt < 8; nt++) {
            oacc[nt][0] *= alpha0; oacc[nt][1] *= alpha0;
            oacc[nt][2] *= alpha1; oacc[nt][3] *= alpha1;
        }

        __syncwarp();

        // O += P @ V  (tf32, 8 k8 steps)
#pragma unroll
        for (int ks = 0; ks < 8; ks++) {
            uint32_t af0 = Ps[prow][ks * 8 + tc];
            uint32_t af1 = Ps[prow + 8][ks * 8 + tc];
            uint32_t af2 = Ps[prow][ks * 8 + tc + 4];
            uint32_t af3 = Ps[prow + 8][ks * 8 + tc + 4];
#pragma unroll
            for (int nt = 0; nt < 8; nt++) {
                uint32_t b0 = Vs[ks * 8 + tc][nt * 8 + gr];
                uint32_t b1 = Vs[ks * 8 + tc + 4][nt * 8 + gr];
                mma_tf32(oacc[nt][0], oacc[nt][1], oacc[nt][2], oacc[nt][3],
                         af0, af1, af2, af3, b0, b1);
            }
        }
    }

    const float inv0 = 1.0f / l0;
    const float inv1 = 1.0f / l1;
    const size_t row0g = (size_t)(b * S_LEN) + qr0;
#pragma unroll
    for (int nt = 0; nt < 8; nt++) {
        const int col = h * DHE + nt * 8 + 2 * tc;
        *(uint32_t*)(g_attn_h + row0g * D_DIM + col) =
            f22h2(oacc[nt][0] * inv0, oacc[nt][1] * inv0);
        *(uint32_t*)(g_attn_h + (row0g + 8) * D_DIM + col) =
            f22h2(oacc[nt][2] * inv1, oacc[nt][3] * inv1);
    }
}

// ---------------- fused double LayerNorm ----------------
__global__ void __launch_bounds__(256) fused_ln2_kernel(
    const float* __restrict__ X, const float* __restrict__ AO,
    const float* __restrict__ g1, const float* __restrict__ b1,
    const float* __restrict__ XW,
    const float* __restrict__ g2, const float* __restrict__ b2,
    float* __restrict__ out)
{
    __shared__ float red[8];
    const int row = blockIdx.x;
    const int t   = threadIdx.x;
    const float invD = 1.f / (float)D_DIM;

    float4 a = *(const float4*)(X  + (size_t)row * D_DIM + t * 4);
    float4 b = *(const float4*)(AO + (size_t)row * D_DIM + t * 4);
    float4 v = make_float4(a.x + b.x, a.y + b.y, a.z + b.z, a.w + b.w);

    float s = v.x + v.y + v.z + v.w;
#pragma unroll
    for (int o = 16; o; o >>= 1) s += __shfl_xor_sync(0xffffffffu, s, o);
    if ((t & 31) == 0) red[t >> 5] = s;
    __syncthreads();
    float tot = 0.f;
#pragma unroll
    for (int i = 0; i < 8; i++) tot += red[i];
    const float mu1 = tot * invD;
    __syncthreads();

    float dx = v.x - mu1, dy = v.y - mu1, dz = v.z - mu1, dw = v.w - mu1;
    float s2 = dx * dx + dy * dy + dz * dz + dw * dw;
#pragma unroll
    for (int o = 16; o; o >>= 1) s2 += __shfl_xor_sync(0xffffffffu, s2, o);
    if ((t & 31) == 0) red[t >> 5] = s2;
    __syncthreads();
    float tot2 = 0.f;
#pragma unroll
    for (int i = 0; i < 8; i++) tot2 += red[i];
    const float inv1v = rsqrtf(tot2 * invD + 1e-5f);
    __syncthreads();

    float4 gg = *(const float4*)(g1 + t * 4);
    float4 bb = *(const float4*)(b1 + t * 4);
    float4 w  = *(const float4*)(XW + (size_t)row * D_DIM + t * 4);
    float4 v2 = make_float4(dx * inv1v * gg.x + bb.x + w.x,
                            dy * inv1v * gg.y + bb.y + w.y,
                            dz * inv1v * gg.z + bb.z + w.z,
                            dw * inv1v * gg.w + bb.w + w.w);

    float s3 = v2.x + v2.y + v2.z + v2.w;
#pragma unroll
    for (int o = 16; o; o >>= 1) s3 += __shfl_xor_sync(0xffffffffu, s3, o);
    if ((t & 31) == 0) red[t >> 5] = s3;
    __syncthreads();
    float tot3 = 0.f;
#pragma unroll
    for (int i = 0; i < 8; i++) tot3 += red[i];
    const float mu2 = tot3 * invD;
    __syncthreads();

    float ex = v2.x - mu2, ey = v2.y - mu2, ez = v2.z - mu2, ew = v2.w - mu2;
    float s4 = ex * ex + ey * ey + ez * ez + ew * ew;
#pragma unroll
    for (int o = 16; o; o >>= 1) s4 += __shfl_xor_sync(0xffffffffu, s4, o);
    if ((t & 31) == 0) red[t >> 5] = s4;
    __syncthreads();
    float tot4 = 0.f;
#pragma unroll
    for (int i = 0; i < 8; i++) tot4 += red[i];
    const float inv2v = rsqrtf(tot4 * invD + 1e-5f);

    float4 g2v = *(const float4*)(g2 + t * 4);
    float4 b2v = *(const float4*)(b2 + t * 4);
    float4 o4 = make_float4(ex * inv2v * g2v.x + b2v.x, ey * inv2v * g2v.y + b2v.y,
                            ez * inv2v * g2v.z + b2v.z, ew * inv2v * g2v.w + b2v.w);
    *(float4*)(out + (size_t)row * D_DIM + t * 4) = o4;
}

// ---------------- launcher ----------------
extern "C" void kernel_launch(void* const* d_in, const int* in_sizes, int n_in,
                              void* d_out, int out_size)
{
    const float* x     = (const float*)d_in[0];
    const float* in_w  = (const float*)d_in[1];
    const float* in_b  = (const float*)d_in[2];
    const float* out_w = (const float*)d_in[3];
    const float* out_b = (const float*)d_in[4];
    const float* ln1g  = (const float*)d_in[5];
    const float* ln1b  = (const float*)d_in[6];
    const float* wr    = (const float*)d_in[7];
    const float* wi    = (const float*)d_in[8];
    const float* ln2g  = (const float*)d_in[9];
    const float* ln2b  = (const float*)d_in[10];
    float* out = (float*)d_out;

    float *attnout, *xwave;
    __half *qkv_h, *xh, *wh_in, *wh_out, *attn_h;
    cudaGetSymbolAddress((void**)&qkv_h,   g_qkv_h);
    cudaGetSymbolAddress((void**)&attnout, g_attnout);
    cudaGetSymbolAddress((void**)&xwave,   g_xwave);
    cudaGetSymbolAddress((void**)&xh,      g_xh);
    cudaGetSymbolAddress((void**)&wh_in,   g_wh_in);
    cudaGetSymbolAddress((void**)&wh_out,  g_wh_out);
    cudaGetSymbolAddress((void**)&attn_h,  g_attn_h);

    // converts (bandwidth-bound, tiny)
    conv_f2h<<<(NTOK * D_DIM / 4 + 255) / 256, 256>>>(x, xh, NTOK * D_DIM);
    conv_f2h<<<(D3 * D_DIM / 4 + 255) / 256, 256>>>(in_w, wh_in, D3 * D_DIM);
    conv_f2h<<<(D_DIM * D_DIM / 4 + 255) / 256, 256>>>(out_w, wh_out, D_DIM * D_DIM);

    // QKV GEMM (half out) + spectral FFT in ONE launch (grouped ordering)
    fused_qkv_spec<<<GEMM_BLOCKS + 1024, 256>>>(xh, wh_in, in_b, qkv_h,
                                                x, wr, wi, xwave);

    // windowed flash attention (fp16 QK + tf32 PV; reads/writes half)
    attn_tc_kernel<<<dim3(S_LEN / 64, NH, B_SZ), 128>>>();

    // output projection (fp16)
    gemm_fp16_pipe<<<dim3(D_DIM / 128, NTOK / 128), 256>>>(attn_h, wh_out, out_b, attnout,
                                                           NTOK, D_DIM, D_DIM);

    // out = LN2( LN1(x + attnout) + xwave )  -- fused
    fused_ln2_kernel<<<NTOK, 256>>>(x, attnout, ln1g, ln1b, xwave, ln2g, ln2b, out);
}

// round 17
// speedup vs baseline: 1.2083x; 1.0841x over previous
#include <cuda_runtime.h>
#include <cuda_fp16.h>
#include <math.h>
#include <stdint.h>

#define S_LEN 2048
#define D_DIM 1024
#define B_SZ  2
#define NH    16
#define DHE   64
#define WIN   128
#define NTOK  (B_SZ * S_LEN)   // 4096
#define D3    (3 * D_DIM)      // 3072

#define SMAP(i) ((i) + ((i) >> 4))

// ---------------- scratch ----------------
__device__ __half g_qkv_h[(size_t)NTOK * D3];
__device__ __half g_attn_h[(size_t)NTOK * D_DIM];
__device__ float  g_attnout[(size_t)NTOK * D_DIM];
__device__ float  g_xwave[(size_t)NTOK * D_DIM];
__device__ __half g_xh[(size_t)NTOK * D_DIM];
__device__ __half g_wh_in[(size_t)D3 * D_DIM];
__device__ __half g_wh_out[(size_t)D_DIM * D_DIM];

// ---------------- helpers ----------------
__device__ __forceinline__ uint32_t smem_u32(const void* p) {
    uint32_t a;
    asm("{ .reg .u64 t; cvta.to.shared.u64 t, %1; cvt.u32.u64 %0, t; }" : "=r"(a) : "l"(p));
    return a;
}
__device__ __forceinline__ void cpasync16(uint32_t dst, const void* src) {
    asm volatile("cp.async.ca.shared.global [%0], [%1], 16;" :: "r"(dst), "l"(src));
}
#define CP_COMMIT() asm volatile("cp.async.commit_group;" ::: "memory")
#define CP_WAIT1()  asm volatile("cp.async.wait_group 1;" ::: "memory")

__device__ __forceinline__ void ldsm_x4(uint32_t& d0, uint32_t& d1, uint32_t& d2,
                                        uint32_t& d3, uint32_t addr)
{
    asm volatile("ldmatrix.sync.aligned.m8n8.x4.shared.b16 {%0,%1,%2,%3}, [%4];"
                 : "=r"(d0), "=r"(d1), "=r"(d2), "=r"(d3) : "r"(addr));
}

__device__ __forceinline__ uint32_t f22h2(float a, float b) {
    __half2 h = __floats2half2_rn(a, b);
    return *(uint32_t*)&h;
}
__device__ __forceinline__ uint32_t f2tf(float f) {
    uint32_t u;
    asm("cvt.rna.tf32.f32 %0, %1;" : "=r"(u) : "f"(f));
    return u;
}
__device__ __forceinline__ void mma_fp16(
    float& c0, float& c1, float& c2, float& c3,
    uint32_t a0, uint32_t a1, uint32_t a2, uint32_t a3,
    uint32_t b0, uint32_t b1)
{
    asm volatile(
        "mma.sync.aligned.m16n8k16.row.col.f32.f16.f16.f32 "
        "{%0,%1,%2,%3}, {%4,%5,%6,%7}, {%8,%9}, {%0,%1,%2,%3};\n"
        : "+f"(c0), "+f"(c1), "+f"(c2), "+f"(c3)
        : "r"(a0), "r"(a1), "r"(a2), "r"(a3), "r"(b0), "r"(b1));
}
__device__ __forceinline__ void mma_tf32(
    float& c0, float& c1, float& c2, float& c3,
    uint32_t a0, uint32_t a1, uint32_t a2, uint32_t a3,
    uint32_t b0, uint32_t b1)
{
    asm volatile(
        "mma.sync.aligned.m16n8k8.row.col.f32.tf32.tf32.f32 "
        "{%0,%1,%2,%3}, {%4,%5,%6,%7}, {%8,%9}, {%0,%1,%2,%3};\n"
        : "+f"(c0), "+f"(c1), "+f"(c2), "+f"(c3)
        : "r"(a0), "r"(a1), "r"(a2), "r"(a3), "r"(b0), "r"(b1));
}

// ---------------- f32 -> f16 convert ----------------
__global__ void __launch_bounds__(256) conv_f2h(const float* __restrict__ src,
                                               __half* __restrict__ dst, int n)
{
    int i = (blockIdx.x * 256 + threadIdx.x) * 4;
    if (i < n) {
        float4 v = *(const float4*)(src + i);
        *(uint2*)(dst + i) = make_uint2(f22h2(v.x, v.y), f22h2(v.z, v.w));
    }
}

// ---------------- complex helpers ----------------
__device__ __forceinline__ float2 cmul(float2 a, float2 b) {
    return make_float2(a.x * b.x - a.y * b.y, a.x * b.y + a.y * b.x);
}
__device__ __forceinline__ float2 cadd(float2 a, float2 b) {
    return make_float2(a.x + b.x, a.y + b.y);
}
__device__ __forceinline__ float2 csub(float2 a, float2 b) {
    return make_float2(a.x - b.x, a.y - b.y);
}

// fused radix-8 Stockham (validated round 13)
template<int SIGN>
__device__ __forceinline__ void fft2048_r8(float2*& cur, float2*& oth)
{
    const float C8 = 0.70710678118654752f;
    const float SG = (float)SIGN;
#pragma unroll
    for (int st = 0; st < 3; st++) {
        const int ls = st * 3;
        const int ss = 1 << ls;
        const int n  = 2048 >> ls;
        const float fn = (2.0f * 3.14159265358979f * SG) / (float)n;
        const int idx = threadIdx.x;
        const int p = idx >> ls;
        const int q = idx & (ss - 1);

        float2 x0 = cur[SMAP(idx)];
        float2 x1 = cur[SMAP(idx + 256)];
        float2 x2 = cur[SMAP(idx + 512)];
        float2 x3 = cur[SMAP(idx + 768)];
        float2 x4 = cur[SMAP(idx + 1024)];
        float2 x5 = cur[SMAP(idx + 1280)];
        float2 x6 = cur[SMAP(idx + 1536)];
        float2 x7 = cur[SMAP(idx + 1792)];

        float2 es = cadd(x0, x4), ed = csub(x0, x4);
        float2 fs = cadd(x2, x6), fd = csub(x2, x6);
        float2 E0 = cadd(es, fs);
        float2 E2 = csub(es, fs);
        float2 E1 = make_float2(ed.x - SG * fd.y, ed.y + SG * fd.x);
        float2 E3 = make_float2(ed.x + SG * fd.y, ed.y - SG * fd.x);
        float2 os = cadd(x1, x5), od = csub(x1, x5);
        float2 gs = cadd(x3, x7), gd = csub(x3, x7);
        float2 O0 = cadd(os, gs);
        float2 O2 = csub(os, gs);
        float2 O1 = make_float2(od.x - SG * gd.y, od.y + SG * gd.x);
        float2 O3 = make_float2(od.x + SG * gd.y, od.y - SG * gd.x);
        float2 t0 = O0;
        float2 t1 = make_float2(C8 * (O1.x - SG * O1.y), C8 * (SG * O1.x + O1.y));
        float2 t2 = make_float2(-SG * O2.y, SG * O2.x);
        float2 t3 = make_float2(C8 * (-O3.x - SG * O3.y), C8 * (SG * O3.x - O3.y));

        float2 X0 = cadd(E0, t0), X4 = csub(E0, t0);
        float2 X1 = cadd(E1, t1), X5 = csub(E1, t1);
        float2 X2 = cadd(E2, t2), X6 = csub(E2, t2);
        float2 X3 = cadd(E3, t3), X7 = csub(E3, t3);

        float sn, cs;
        __sincosf(fn * (float)p, &sn, &cs);
        const float2 w1 = make_float2(cs, sn);
        const float2 w2 = cmul(w1, w1);
        const float2 w3 = cmul(w1, w2);
        const float2 w4 = cmul(w2, w2);
        const float2 w5 = cmul(w2, w3);
        const float2 w6 = cmul(w3, w3);
        const float2 w7 = cmul(w3, w4);

        const int ob = q + 8 * ss * p;
        oth[SMAP(ob)]          = X0;
        oth[SMAP(ob + ss)]     = cmul(X1, w1);
        oth[SMAP(ob + 2 * ss)] = cmul(X2, w2);
        oth[SMAP(ob + 3 * ss)] = cmul(X3, w3);
        oth[SMAP(ob + 4 * ss)] = cmul(X4, w4);
        oth[SMAP(ob + 5 * ss)] = cmul(X5, w5);
        oth[SMAP(ob + 6 * ss)] = cmul(X6, w6);
        oth[SMAP(ob + 7 * ss)] = cmul(X7, w7);

        __syncthreads();
        float2* tmp = cur; cur = oth; oth = tmp;
    }
#pragma unroll
    for (int ii = 0; ii < 2; ii++) {
        const int qq = threadIdx.x + 256 * ii;
        float2 x0 = cur[SMAP(qq)];
        float2 x1 = cur[SMAP(qq + 512)];
        float2 x2 = cur[SMAP(qq + 1024)];
        float2 x3 = cur[SMAP(qq + 1536)];
        float2 a0 = cadd(x0, x2), a1 = csub(x0, x2);
        float2 b0 = cadd(x1, x3), u = csub(x1, x3);
        float2 b1 = make_float2(-SG * u.y, SG * u.x);
        oth[SMAP(qq)]        = cadd(a0, b0);
        oth[SMAP(qq + 512)]  = cadd(a1, b1);
        oth[SMAP(qq + 1024)] = csub(a0, b0);
        oth[SMAP(qq + 1536)] = csub(a1, b1);
    }
    __syncthreads();
    { float2* tmp = cur; cur = oth; oth = tmp; }
}

// ---------------- fused QKV GEMM + spectral (grouped ordering) ----------------
#define LDP 20
#define STG 3
#define STGB (128 * LDP * 4)                   // stage size in bytes
#define GEMM_BX (D3 / 128)                     // 24
#define GEMM_BLOCKS (GEMM_BX * (NTOK / 128))   // 768

union __align__(16) SmemU {
    struct { uint32_t As2[STG][128][LDP]; uint32_t Ws2[STG][128][LDP]; } g;  // 61440 B
    struct { float2 bufA[2176]; float2 bufB[2176]; } s;                      // 34816 B
};

__global__ void __launch_bounds__(256, 2) fused_qkv_spec(
    const __half* __restrict__ A, const __half* __restrict__ W,
    const float* __restrict__ bias, __half* __restrict__ C,
    const float* __restrict__ x, const float* __restrict__ wr,
    const float* __restrict__ wi, float* __restrict__ xwave)
{
    __shared__ SmemU u;
    const int t = threadIdx.x;

    if (blockIdx.x < GEMM_BLOCKS) {
        // ============ QKV GEMM path (M=NTOK, N=D3, K=D_DIM) -> half output ============
        const int  N = D3, K = D_DIM;
        const int row0 = (blockIdx.x / GEMM_BX) * 128;
        const int col0 = (blockIdx.x % GEMM_BX) * 128;
        const int warp = t >> 5;
        const int lane = t & 31;
        const int gr   = lane >> 2;
        const int tc   = lane & 3;
        const int m0w  = (warp >> 2) * 64;
        const int n0w  = (warp & 3) * 32;

        const int r0c = t >> 2;          const int c0c = t & 3;
        const int r1c = (t + 256) >> 2;  const int c1c = (t + 256) & 3;

        const __half* Ar0 = A + (size_t)(row0 + r0c) * K + c0c * 8;
        const __half* Ar1 = A + (size_t)(row0 + r1c) * K + c1c * 8;
        const __half* Wr0 = W + (size_t)(col0 + r0c) * K + c0c * 8;
        const __half* Wr1 = W + (size_t)(col0 + r1c) * K + c1c * 8;

        // ldmatrix per-thread address components
        const int local = lane & 7;
        const int sel   = lane >> 3;
        const uint32_t rowA = local + (sel & 1) * 8;
        const uint32_t colA = (sel >> 1) * 4;
        const uint32_t rowB = local + (sel >> 1) * 8;
        const uint32_t colB = (sel & 1) * 4;
        const uint32_t aBase = smem_u32(&u.g.As2[0][0][0]) + (m0w + rowA) * (LDP * 4) + colA * 4;
        const uint32_t bBase = smem_u32(&u.g.Ws2[0][0][0]) + (n0w + rowB) * (LDP * 4) + colB * 4;

        float acc[4][4][4];
#pragma unroll
        for (int mi = 0; mi < 4; mi++)
#pragma unroll
            for (int ni = 0; ni < 4; ni++)
#pragma unroll
                for (int r = 0; r < 4; r++) acc[mi][ni][r] = 0.f;

        const int ntiles = K >> 5;

#pragma unroll
        for (int s = 0; s < 2; s++) {
            const int k0 = s << 5;
            cpasync16(smem_u32(&u.g.As2[s][r0c][c0c * 4]), Ar0 + k0);
            cpasync16(smem_u32(&u.g.As2[s][r1c][c1c * 4]), Ar1 + k0);
            cpasync16(smem_u32(&u.g.Ws2[s][r0c][c0c * 4]), Wr0 + k0);
            cpasync16(smem_u32(&u.g.Ws2[s][r1c][c1c * 4]), Wr1 + k0);
            CP_COMMIT();
        }

        int cb = 0, nst = 2;
        for (int kt = 0; kt < ntiles; kt++) {
            CP_WAIT1();
            __syncthreads();

            if (kt + 2 < ntiles) {
                const int k0 = (kt + 2) << 5;
                cpasync16(smem_u32(&u.g.As2[nst][r0c][c0c * 4]), Ar0 + k0);
                cpasync16(smem_u32(&u.g.As2[nst][r1c][c1c * 4]), Ar1 + k0);
                cpasync16(smem_u32(&u.g.Ws2[nst][r0c][c0c * 4]), Wr0 + k0);
                cpasync16(smem_u32(&u.g.Ws2[nst][r1c][c1c * 4]), Wr1 + k0);
            }
            CP_COMMIT();

            const uint32_t aS = aBase + cb * STGB;
            const uint32_t bS = bBase + cb * STGB;
#pragma unroll
            for (int kk = 0; kk < 2; kk++) {
                uint32_t af[4][4];
#pragma unroll
                for (int mi = 0; mi < 4; mi++)
                    ldsm_x4(af[mi][0], af[mi][1], af[mi][2], af[mi][3],
                            aS + mi * 16 * (LDP * 4) + kk * 32);
                uint32_t bf[4][2];
#pragma unroll
                for (int np = 0; np < 2; np++)
                    ldsm_x4(bf[2 * np][0], bf[2 * np][1], bf[2 * np + 1][0], bf[2 * np + 1][1],
                            bS + np * 16 * (LDP * 4) + kk * 32);
#pragma unroll
                for (int mi = 0; mi < 4; mi++)
#pragma unroll
                    for (int ni = 0; ni < 4; ni++)
                        mma_fp16(acc[mi][ni][0], acc[mi][ni][1], acc[mi][ni][2], acc[mi][ni][3],
                                 af[mi][0], af[mi][1], af[mi][2], af[mi][3],
                                 bf[ni][0], bf[ni][1]);
            }

            cb  = (cb  + 1) % STG;
            nst = (nst + 1) % STG;
        }

        // epilogue: half output
#pragma unroll
        for (int mi = 0; mi < 4; mi++) {
#pragma unroll
            for (int ni = 0; ni < 4; ni++) {
                const int r = row0 + m0w + mi * 16 + gr;
                const int c = col0 + n0w + ni * 8 + tc * 2;
                float2 bs = *(const float2*)(bias + c);
                *(uint32_t*)(C + (size_t)r * N + c) =
                    f22h2(acc[mi][ni][0] + bs.x, acc[mi][ni][1] + bs.y);
                *(uint32_t*)(C + (size_t)(r + 8) * N + c) =
                    f22h2(acc[mi][ni][2] + bs.x, acc[mi][ni][3] + bs.y);
            }
        }
    } else {
        // ================= spectral path =================
        const int sid = blockIdx.x - GEMM_BLOCKS;
        const int d0 = (sid & 511) * 2;
        const int b  = sid >> 9;

        float2* bufA = u.s.bufA;
        float2* bufB = u.s.bufB;

        const float* xp = x + (size_t)b * S_LEN * D_DIM + d0;
        for (int s = t; s < 2048; s += 256)
            bufA[SMAP(s)] = *(const float2*)(xp + (size_t)s * D_DIM);
        __syncthreads();

        float2* cur = bufA;
        float2* oth = bufB;
        fft2048_r8<-1>(cur, oth);

        for (int k = t; k < 2048; k += 256) {
            const int km = (2048 - k) & 2047;
            float2 Zk = cur[SMAP(k)];
            float2 Zm = cur[SMAP(km)];
            float2 Av = make_float2(0.5f * (Zk.x + Zm.x), 0.5f * (Zk.y - Zm.y));
            float2 Bc = make_float2(0.5f * (Zk.y + Zm.y), -0.5f * (Zk.x - Zm.x));
            const int   kf  = (k <= 1024) ? k : 2048 - k;
            const float sgn = (k <= 1024) ? 1.f : -1.f;
            float2 wrp = *(const float2*)(wr + (size_t)kf * D_DIM + d0);
            float2 wip = *(const float2*)(wi + (size_t)kf * D_DIM + d0);
            float2 c1 = make_float2(wrp.x, sgn * wip.x);
            float2 c2 = make_float2(wrp.y, sgn * wip.y);
            if (k == 0 || k == 1024) { c1.y = 0.f; c2.y = 0.f; }
            float2 Y1 = cmul(Av, c1);
            float2 Y2 = cmul(Bc, c2);
            oth[SMAP(k)] = make_float2(Y1.x - Y2.y, Y1.y + Y2.x);
        }
        __syncthreads();
        { float2* tmp = cur; cur = oth; oth = tmp; }

        fft2048_r8<1>(cur, oth);

        float* dst = xwave + (size_t)b * S_LEN * D_DIM + d0;
        const float invn = 1.0f / 2048.0f;
        for (int s = t; s < 2048; s += 256) {
            float2 r = cur[SMAP(s)];
            *(float2*)(dst + (size_t)s * D_DIM) = make_float2(r.x * invn, r.y * invn);
        }
    }
}

// ---------------- fp16 GEMM, 3-stage cp.async pipeline + ldmatrix (out-proj) ----------------
__global__ void __launch_bounds__(256, 2) gemm_fp16_pipe(
    const __half* __restrict__ A, const __half* __restrict__ W,
    const float* __restrict__ bias, float* __restrict__ C,
    int M, int N, int K)
{
    __shared__ __align__(16) uint32_t As2[STG][128][LDP];
    __shared__ __align__(16) uint32_t Ws2[STG][128][LDP];

    const int row0 = blockIdx.y * 128;
    const int col0 = blockIdx.x * 128;
    const int t    = threadIdx.x;
    const int warp = t >> 5;
    const int lane = t & 31;
    const int gr   = lane >> 2;
    const int tc   = lane & 3;
    const int m0w  = (warp >> 2) * 64;
    const int n0w  = (warp & 3) * 32;

    const int r0c = t >> 2;          const int c0c = t & 3;
    const int r1c = (t + 256) >> 2;  const int c1c = (t + 256) & 3;

    const __half* Ar0 = A + (size_t)(row0 + r0c) * K + c0c * 8;
    const __half* Ar1 = A + (size_t)(row0 + r1c) * K + c1c * 8;
    const __half* Wr0 = W + (size_t)(col0 + r0c) * K + c0c * 8;
    const __half* Wr1 = W + (size_t)(col0 + r1c) * K + c1c * 8;

    const int local = lane & 7;
    const int sel   = lane >> 3;
    const uint32_t rowA = local + (sel & 1) * 8;
    const uint32_t colA = (sel >> 1) * 4;
    const uint32_t rowB = local + (sel >> 1) * 8;
    const uint32_t colB = (sel & 1) * 4;
    const uint32_t aBase = smem_u32(&As2[0][0][0]) + (m0w + rowA) * (LDP * 4) + colA * 4;
    const uint32_t bBase = smem_u32(&Ws2[0][0][0]) + (n0w + rowB) * (LDP * 4) + colB * 4;

    float acc[4][4][4];
#pragma unroll
    for (int mi = 0; mi < 4; mi++)
#pragma unroll
        for (int ni = 0; ni < 4; ni++)
#pragma unroll
            for (int r = 0; r < 4; r++) acc[mi][ni][r] = 0.f;

    const int ntiles = K >> 5;

#pragma unroll
    for (int s = 0; s < 2; s++) {
        const int k0 = s << 5;
        cpasync16(smem_u32(&As2[s][r0c][c0c * 4]), Ar0 + k0);
        cpasync16(smem_u32(&As2[s][r1c][c1c * 4]), Ar1 + k0);
        cpasync16(smem_u32(&Ws2[s][r0c][c0c * 4]), Wr0 + k0);
        cpasync16(smem_u32(&Ws2[s][r1c][c1c * 4]), Wr1 + k0);
        CP_COMMIT();
    }

    int cb = 0, nst = 2;
    for (int kt = 0; kt < ntiles; kt++) {
        CP_WAIT1();
        __syncthreads();

        if (kt + 2 < ntiles) {
            const int k0 = (kt + 2) << 5;
            cpasync16(smem_u32(&As2[nst][r0c][c0c * 4]), Ar0 + k0);
            cpasync16(smem_u32(&As2[nst][r1c][c1c * 4]), Ar1 + k0);
            cpasync16(smem_u32(&Ws2[nst][r0c][c0c * 4]), Wr0 + k0);
            cpasync16(smem_u32(&Ws2[nst][r1c][c1c * 4]), Wr1 + k0);
        }
        CP_COMMIT();

        const uint32_t aS = aBase + cb * STGB;
        const uint32_t bS = bBase + cb * STGB;
#pragma unroll
        for (int kk = 0; kk < 2; kk++) {
            uint32_t af[4][4];
#pragma unroll
            for (int mi = 0; mi < 4; mi++)
                ldsm_x4(af[mi][0], af[mi][1], af[mi][2], af[mi][3],
                        aS + mi * 16 * (LDP * 4) + kk * 32);
            uint32_t bf[4][2];
#pragma unroll
            for (int np = 0; np < 2; np++)
                ldsm_x4(bf[2 * np][0], bf[2 * np][1], bf[2 * np + 1][0], bf[2 * np + 1][1],
                        bS + np * 16 * (LDP * 4) + kk * 32);
#pragma unroll
            for (int mi = 0; mi < 4; mi++)
#pragma unroll
                for (int ni = 0; ni < 4; ni++)
                    mma_fp16(acc[mi][ni][0], acc[mi][ni][1], acc[mi][ni][2], acc[mi][ni][3],
                             af[mi][0], af[mi][1], af[mi][2], af[mi][3],
                             bf[ni][0], bf[ni][1]);
        }

        cb  = (cb  + 1) % STG;
        nst = (nst + 1) % STG;
    }

#pragma unroll
    for (int mi = 0; mi < 4; mi++) {
#pragma unroll
        for (int ni = 0; ni < 4; ni++) {
            const int r = row0 + m0w + mi * 16 + gr;
            const int c = col0 + n0w + ni * 8 + tc * 2;
            float2 bs = *(const float2*)(bias + c);
            float2 v0 = make_float2(acc[mi][ni][0] + bs.x, acc[mi][ni][1] + bs.y);
            float2 v1 = make_float2(acc[mi][ni][2] + bs.x, acc[mi][ni][3] + bs.y);
            *(float2*)(C + (size_t)r * N + c)       = v0;
            *(float2*)(C + (size_t)(r + 8) * N + c) = v1;
        }
    }
}

// ---------------- windowed flash attention: fp16 QK^T + tf32 PV (unchanged) ----------------
#define KPAD 36
#define VPAD 72
#define PPAD 68
__global__ void __launch_bounds__(128) attn_tc_kernel()
{
    __shared__ uint32_t Qs[64][KPAD];
    __shared__ uint32_t Ks[64][KPAD];
    __shared__ uint32_t Vs[64][VPAD];
    __shared__ uint32_t Ps[64][PPAD];

    const int q0  = blockIdx.x * 64;
    const int h   = blockIdx.y;
    const int b   = blockIdx.z;
    const int t   = threadIdx.x;
    const int wid = t >> 5;
    const int lane = t & 31;
    const int gr  = lane >> 2;
    const int tc  = lane & 3;

    const __half2 qscale = __float2half2_rn(0.125f);

#pragma unroll
    for (int i = 0; i < 8; i++) {
        int s   = t + 128 * i;
        int row = s >> 4;
        int cu  = (s & 15) * 2;
        const __half* src = g_qkv_h + (size_t)(b * S_LEN + q0 + row) * D3 + h * DHE + cu * 2;
        uint2 v = *(const uint2*)src;
        __half2 h0 = __hmul2(*(__half2*)&v.x, qscale);
        __half2 h1 = __hmul2(*(__half2*)&v.y, qscale);
        *(uint2*)&Qs[row][cu] = make_uint2(*(uint32_t*)&h0, *(uint32_t*)&h1);
    }

    const int qr0 = q0 + wid * 16 + gr;
    const int qr1 = qr0 + 8;

    float m0 = -1e30f, m1 = -1e30f, l0 = 0.f, l1 = 0.f;
    float oacc[8][4];
#pragma unroll
    for (int nt = 0; nt < 8; nt++)
#pragma unroll
        for (int r = 0; r < 4; r++) oacc[nt][r] = 0.f;

    const int kstart = (q0 - WIN > 0) ? (q0 - WIN) : 0;
    const int kend   = (q0 + 64 + WIN < S_LEN) ? (q0 + 64 + WIN) : S_LEN;

    for (int kc = kstart; kc < kend; kc += 64) {
        __syncthreads();
#pragma unroll
        for (int i = 0; i < 8; i++) {
            int s   = t + 128 * i;
            int row = s >> 4;
            int cu  = (s & 15) * 2;
            const __half* kp = g_qkv_h + (size_t)(b * S_LEN + kc + row) * D3 + D_DIM + h * DHE + cu * 2;
            uint2 kv = *(const uint2*)kp;
            *(uint2*)&Ks[row][cu] = kv;
            uint2 vv = *(const uint2*)(kp + D_DIM);
            float2 f0 = __half22float2(*(__half2*)&vv.x);
            float2 f1 = __half22float2(*(__half2*)&vv.y);
            const int dh0 = (s & 15) * 4;
            *(uint4*)&Vs[row][dh0] = make_uint4(f2tf(f0.x), f2tf(f0.y), f2tf(f1.x), f2tf(f1.y));
        }
        __syncthreads();

        float sacc[8][4];
#pragma unroll
        for (int nt = 0; nt < 8; nt++)
#pragma unroll
            for (int r = 0; r < 4; r++) sacc[nt][r] = 0.f;

#pragma unroll
        for (int ks = 0; ks < 4; ks++) {
            const int qrow = wid * 16 + gr;
            uint32_t af0 = Qs[qrow][ks * 8 + tc];
            uint32_t af1 = Qs[qrow + 8][ks * 8 + tc];
            uint32_t af2 = Qs[qrow][ks * 8 + tc + 4];
            uint32_t af3 = Qs[qrow + 8][ks * 8 + tc + 4];
#pragma unroll
            for (int nt = 0; nt < 8; nt++) {
                uint32_t b0 = Ks[nt * 8 + gr][ks * 8 + tc];
                uint32_t b1 = Ks[nt * 8 + gr][ks * 8 + tc + 4];
                mma_fp16(sacc[nt][0], sacc[nt][1], sacc[nt][2], sacc[nt][3],
                         af0, af1, af2, af3, b0, b1);
            }
        }

        float mx0 = m0, mx1 = m1;
#pragma unroll
        for (int nt = 0; nt < 8; nt++) {
            const int c = kc + nt * 8 + 2 * tc;
            if (c     < qr0 - WIN || c     > qr0 + WIN) sacc[nt][0] = -1e30f;
            if (c + 1 < qr0 - WIN || c + 1 > qr0 + WIN) sacc[nt][1] = -1e30f;
            if (c     < qr1 - WIN || c     > qr1 + WIN) sacc[nt][2] = -1e30f;
            if (c + 1 < qr1 - WIN || c + 1 > qr1 + WIN) sacc[nt][3] = -1e30f;
            mx0 = fmaxf(mx0, fmaxf(sacc[nt][0], sacc[nt][1]));
            mx1 = fmaxf(mx1, fmaxf(sacc[nt][2], sacc[nt][3]));
        }
        mx0 = fmaxf(mx0, __shfl_xor_sync(0xffffffffu, mx0, 1));
        mx0 = fmaxf(mx0, __shfl_xor_sync(0xffffffffu, mx0, 2));
        mx1 = fmaxf(mx1, __shfl_xor_sync(0xffffffffu, mx1, 1));
        mx1 = fmaxf(mx1, __shfl_xor_sync(0xffffffffu, mx1, 2));

        const float alpha0 = __expf(m0 - mx0);
        const float alpha1 = __expf(m1 - mx1);

        float ps0 = 0.f, ps1 = 0.f;
        const int prow = wid * 16 + gr;
#pragma unroll
        for (int nt = 0; nt < 8; nt++) {
            float p00 = __expf(sacc[nt][0] - mx0);
            float p01 = __expf(sacc[nt][1] - mx0);
            float p10 = __expf(sacc[nt][2] - mx1);
            float p11 = __expf(sacc[nt][3] - mx1);
            ps0 += p00 + p01;
            ps1 += p10 + p11;
            *(uint2*)&Ps[prow][nt * 8 + 2 * tc]     = make_uint2(f2tf(p00), f2tf(p01));
            *(uint2*)&Ps[prow + 8][nt * 8 + 2 * tc] = make_uint2(f2tf(p10), f2tf(p11));
        }
        ps0 += __shfl_xor_sync(0xffffffffu, ps0, 1);
        ps0 += __shfl_xor_sync(0xffffffffu, ps0, 2);
        ps1 += __shfl_xor_sync(0xffffffffu, ps1, 1);
        ps1 += __shfl_xor_sync(0xffffffffu, ps1, 2);

        l0 = l0 * alpha0 + ps0;  m0 = mx0;
        l1 = l1 * alpha1 + ps1;  m1 = mx1;

#pragma unroll
        for (int nt = 0; nt < 8; nt++) {
            oacc[nt][0] *= alpha0; oacc[nt][1] *= alpha0;
            oacc[nt][2] *= alpha1; oacc[nt][3] *= alpha1;
        }

        __syncwarp();

#pragma unroll
        for (int ks = 0; ks < 8; ks++) {
            uint32_t af0 = Ps[prow][ks * 8 + tc];
            uint32_t af1 = Ps[prow + 8][ks * 8 + tc];
            uint32_t af2 = Ps[prow][ks * 8 + tc + 4];
            uint32_t af3 = Ps[prow + 8][ks * 8 + tc + 4];
#pragma unroll
            for (int nt = 0; nt < 8; nt++) {
                uint32_t b0 = Vs[ks * 8 + tc][nt * 8 + gr];
                uint32_t b1 = Vs[ks * 8 + tc + 4][nt * 8 + gr];
                mma_tf32(oacc[nt][0], oacc[nt][1], oacc[nt][2], oacc[nt][3],
                         af0, af1, af2, af3, b0, b1);
            }
        }
    }

    const float inv0 = 1.0f / l0;
    const float inv1 = 1.0f / l1;
    const size_t row0g = (size_t)(b * S_LEN) + qr0;
#pragma unroll
    for (int nt = 0; nt < 8; nt++) {
        const int col = h * DHE + nt * 8 + 2 * tc;
        *(uint32_t*)(g_attn_h + row0g * D_DIM + col) =
            f22h2(oacc[nt][0] * inv0, oacc[nt][1] * inv0);
        *(uint32_t*)(g_attn_h + (row0g + 8) * D_DIM + col) =
            f22h2(oacc[nt][2] * inv1, oacc[nt][3] * inv1);
    }
}

// ---------------- fused double LayerNorm (unchanged) ----------------
__global__ void __launch_bounds__(256) fused_ln2_kernel(
    const float* __restrict__ X, const float* __restrict__ AO,
    const float* __restrict__ g1, const float* __restrict__ b1,
    const float* __restrict__ XW,
    const float* __restrict__ g2, const float* __restrict__ b2,
    float* __restrict__ out)
{
    __shared__ float red[8];
    const int row = blockIdx.x;
    const int t   = threadIdx.x;
    const float invD = 1.f / (float)D_DIM;

    float4 a = *(const float4*)(X  + (size_t)row * D_DIM + t * 4);
    float4 b = *(const float4*)(AO + (size_t)row * D_DIM + t * 4);
    float4 v = make_float4(a.x + b.x, a.y + b.y, a.z + b.z, a.w + b.w);

    float s = v.x + v.y + v.z + v.w;
#pragma unroll
    for (int o = 16; o; o >>= 1) s += __shfl_xor_sync(0xffffffffu, s, o);
    if ((t & 31) == 0) red[t >> 5] = s;
    __syncthreads();
    float tot = 0.f;
#pragma unroll
    for (int i = 0; i < 8; i++) tot += red[i];
    const float mu1 = tot * invD;
    __syncthreads();

    float dx = v.x - mu1, dy = v.y - mu1, dz = v.z - mu1, dw = v.w - mu1;
    float s2 = dx * dx + dy * dy + dz * dz + dw * dw;
#pragma unroll
    for (int o = 16; o; o >>= 1) s2 += __shfl_xor_sync(0xffffffffu, s2, o);
    if ((t & 31) == 0) red[t >> 5] = s2;
    __syncthreads();
    float tot2 = 0.f;
#pragma unroll
    for (int i = 0; i < 8; i++) tot2 += red[i];
    const float inv1v = rsqrtf(tot2 * invD + 1e-5f);
    __syncthreads();

    float4 gg = *(const float4*)(g1 + t * 4);
    float4 bb = *(const float4*)(b1 + t * 4);
    float4 w  = *(const float4*)(XW + (size_t)row * D_DIM + t * 4);
    float4 v2 = make_float4(dx * inv1v * gg.x + bb.x + w.x,
                            dy * inv1v * gg.y + bb.y + w.y,
                            dz * inv1v * gg.z + bb.z + w.z,
                            dw * inv1v * gg.w + bb.w + w.w);

    float s3 = v2.x + v2.y + v2.z + v2.w;
#pragma unroll
    for (int o = 16; o; o >>= 1) s3 += __shfl_xor_sync(0xffffffffu, s3, o);
    if ((t & 31) == 0) red[t >> 5] = s3;
    __syncthreads();
    float tot3 = 0.f;
#pragma unroll
    for (int i = 0; i < 8; i++) tot3 += red[i];
    const float mu2 = tot3 * invD;
    __syncthreads();

    float ex = v2.x - mu2, ey = v2.y - mu2, ez = v2.z - mu2, ew = v2.w - mu2;
    float s4 = ex * ex + ey * ey + ez * ez + ew * ew;
#pragma unroll
    for (int o = 16; o; o >>= 1) s4 += __shfl_xor_sync(0xffffffffu, s4, o);
    if ((t & 31) == 0) red[t >> 5] = s4;
    __syncthreads();
    float tot4 = 0.f;
#pragma unroll
    for (int i = 0; i < 8; i++) tot4 += red[i];
    const float inv2v = rsqrtf(tot4 * invD + 1e-5f);

    float4 g2v = *(const float4*)(g2 + t * 4);
    float4 b2v = *(const float4*)(b2 + t * 4);
    float4 o4 = make_float4(ex * inv2v * g2v.x + b2v.x, ey * inv2v * g2v.y + b2v.y,
                            ez * inv2v * g2v.z + b2v.z, ew * inv2v * g2v.w + b2v.w);
    *(float4*)(out + (size_t)row * D_DIM + t * 4) = o4;
}

// ---------------- launcher ----------------
extern "C" void kernel_launch(void* const* d_in, const int* in_sizes, int n_in,
                              void* d_out, int out_size)
{
    const float* x     = (const float*)d_in[0];
    const float* in_w  = (const float*)d_in[1];
    const float* in_b  = (const float*)d_in[2];
    const float* out_w = (const float*)d_in[3];
    const float* out_b = (const float*)d_in[4];
    const float* ln1g  = (const float*)d_in[5];
    const float* ln1b  = (const float*)d_in[6];
    const float* wr    = (const float*)d_in[7];
    const float* wi    = (const float*)d_in[8];
    const float* ln2g  = (const float*)d_in[9];
    const float* ln2b  = (const float*)d_in[10];
    float* out = (float*)d_out;

    float *attnout, *xwave;
    __half *qkv_h, *xh, *wh_in, *wh_out, *attn_h;
    cudaGetSymbolAddress((void**)&qkv_h,   g_qkv_h);
    cudaGetSymbolAddress((void**)&attnout, g_attnout);
    cudaGetSymbolAddress((void**)&xwave,   g_xwave);
    cudaGetSymbolAddress((void**)&xh,      g_xh);
    cudaGetSymbolAddress((void**)&wh_in,   g_wh_in);
    cudaGetSymbolAddress((void**)&wh_out,  g_wh_out);
    cudaGetSymbolAddress((void**)&attn_h,  g_attn_h);

    // converts (bandwidth-bound, tiny)
    conv_f2h<<<(NTOK * D_DIM / 4 + 255) / 256, 256>>>(x, xh, NTOK * D_DIM);
    conv_f2h<<<(D3 * D_DIM / 4 + 255) / 256, 256>>>(in_w, wh_in, D3 * D_DIM);
    conv_f2h<<<(D_DIM * D_DIM / 4 + 255) / 256, 256>>>(out_w, wh_out, D_DIM * D_DIM);

    // QKV GEMM (half out) + spectral FFT in ONE launch (grouped ordering)
    fused_qkv_spec<<<GEMM_BLOCKS + 1024, 256>>>(xh, wh_in, in_b, qkv_h,
                                                x, wr, wi, xwave);

    // windowed flash attention (fp16 QK + tf32 PV)
    attn_tc_kernel<<<dim3(S_LEN / 64, NH, B_SZ), 128>>>();

    // output projection (fp16 + ldmatrix)
    gemm_fp16_pipe<<<dim3(D_DIM / 128, NTOK / 128), 256>>>(attn_h, wh_out, out_b, attnout,
                                                           NTOK, D_DIM, D_DIM);

    // out = LN2( LN1(x + attnout) + xwave )  -- fused
    fused_ln2_kernel<<<NTOK, 256>>>(x, attnout, ln1g, ln1b, xwave, ln2g, ln2b, out);
}